// round 12
// baseline (speedup 1.0000x reference)
#include <cuda_runtime.h>
#include <cuda_bf16.h>
#include <math.h>
#include <float.h>
#include <stdint.h>

// ---------------- problem constants ----------------
#define BT   4096
#define KS   2048
#define KT   4096
#define VOC  32000
// ---------------- tiling ----------------
#define BM   128
#define BN   256
#define BK   128           // k-chunk (bf16 elems) = 2 x 128B subtiles per row
#define NT   125           // 32000/256 vocab tiles
#define NT4  500           // NT * 4 warp_n slices
#define NPAD 1024
#define NCH_S (KS/BK)      // 16 (even -> stage ring parity continues across tiles)
#define NCH_T (KT/BK)      // 32 (even)
#define NST  2
#define STAGE_B (BM*256 + BN*256)      // 96 KB
#define SMEM_BYTES (NST * STAGE_B)     // 192 KB
#define NCTA (32 * NT)                 // 4000
#define NWORK (2 * NCTA)               // 8000
#define GRID 148                       // persistent: all CTAs co-resident (1/SM)

// ---------------- static device scratch ----------------
__device__ __nv_bfloat16 g_sin_bf[(size_t)BT * KS];
__device__ __nv_bfloat16 g_tin_bf[(size_t)BT * KT];
__device__ __nv_bfloat16 g_sw_bf [(size_t)VOC * KS];
__device__ __nv_bfloat16 g_tw_bf [(size_t)VOC * KT];

__device__ uint4 g_slog[(size_t)NCTA * 256 * 16];   // 262 MB: S fragments, reg-layout
__device__ int   g_sdone[NCTA];                     // per-S-tile completion flags

__device__ float g_m [(size_t)BT * NPAD];
__device__ float g_z [(size_t)BT * NPAD];
__device__ float g_d [(size_t)BT * NPAD];
__device__ float g_ss[(size_t)BT * NPAD];
__device__ float g_tt[(size_t)BT * NPAD];
__device__ float g_row[BT * 2];

// ---------------- PTX helpers ----------------
__device__ __forceinline__ uint32_t smem_u32(const void* p) {
    uint32_t a;
    asm("{ .reg .u64 t; cvta.to.shared.u64 t, %1; cvt.u32.u64 %0, t; }" : "=r"(a) : "l"(p));
    return a;
}
#define SWZ(o) ((o) ^ (((o) >> 3) & 0x70))

#define CP16(dst, src) \
    asm volatile("cp.async.cg.shared.global [%0], [%1], 16;" :: "r"(dst), "l"(src) : "memory")
#define CP_COMMIT() asm volatile("cp.async.commit_group;" ::: "memory")
#define CP_WAIT(n)  asm volatile("cp.async.wait_group %0;" :: "n"(n) : "memory")

#define LDSM4(r0, r1, r2, r3, a) \
    asm volatile("ldmatrix.sync.aligned.m8n8.x4.shared.b16 {%0,%1,%2,%3}, [%4];" \
        : "=r"(r0), "=r"(r1), "=r"(r2), "=r"(r3) : "r"(a))

#define MMA16816(d, a, b) \
    asm volatile("mma.sync.aligned.m16n8k16.row.col.f32.bf16.bf16.f32 " \
        "{%0,%1,%2,%3}, {%4,%5,%6,%7}, {%8,%9}, {%0,%1,%2,%3};" \
        : "+f"((d)[0]), "+f"((d)[1]), "+f"((d)[2]), "+f"((d)[3]) \
        : "r"((a)[0]), "r"((a)[1]), "r"((a)[2]), "r"((a)[3]), \
          "r"((b)[0]), "r"((b)[1]))

// ---------------- fused fp32 -> bf16 conversion (serial, round-10 proven) ----
#define N_SIN ((size_t)BT * KS)
#define N_TIN ((size_t)BT * KT)
#define N_SW  ((size_t)VOC * KS)
#define N_TW  ((size_t)VOC * KT)
#define N_TOT (N_SIN + N_TIN + N_SW + N_TW)

__global__ void cvt_all_kernel(const float* __restrict__ s_in,
                               const float* __restrict__ t_in,
                               const float* __restrict__ s_w,
                               const float* __restrict__ t_w) {
    // reset S-tile completion flags (deterministic across graph replays)
    if (blockIdx.x == 0) {
        for (int i = threadIdx.x; i < NCTA; i += 256) g_sdone[i] = 0;
    }
    size_t i = ((size_t)blockIdx.x * blockDim.x + threadIdx.x) * 4;
    size_t stride = (size_t)gridDim.x * blockDim.x * 4;
    for (; i < N_TOT; i += stride) {
        const float* src; __nv_bfloat16* dst; size_t off;
        if (i < N_SIN)                    { src = s_in; dst = g_sin_bf; off = i; }
        else if (i < N_SIN + N_TIN)       { src = t_in; dst = g_tin_bf; off = i - N_SIN; }
        else if (i < N_SIN + N_TIN + N_SW){ src = s_w;  dst = g_sw_bf;  off = i - N_SIN - N_TIN; }
        else                              { src = t_w;  dst = g_tw_bf;  off = i - N_SIN - N_TIN - N_SW; }
        float4 v = *reinterpret_cast<const float4*>(src + off);
        __nv_bfloat162 a = __float22bfloat162_rn(make_float2(v.x, v.y));
        __nv_bfloat162 b = __float22bfloat162_rn(make_float2(v.z, v.w));
        uint2 o;
        o.x = *reinterpret_cast<uint32_t*>(&a);
        o.y = *reinterpret_cast<uint32_t*>(&b);
        *reinterpret_cast<uint2*>(dst + off) = o;
    }
}

// ---------------- bulk chunk loader (first tile prologue only) --------------
__device__ __forceinline__ void load_chunk(const __nv_bfloat16* __restrict__ Ab,
                                           const __nv_bfloat16* __restrict__ Bb,
                                           int K, int k0, int st, uint32_t sb,
                                           int row0, int col0, int tid) {
    uint32_t sA = sb + st * STAGE_B;
    uint32_t sB = sA + BM * 256;
#pragma unroll
    for (int sub = 0; sub < 2; sub++) {
        int ke = k0 + sub * 64;
        uint32_t aBase = sA + sub * (BM * 128);
        uint32_t bBase = sB + sub * (BN * 128);
#pragma unroll
        for (int i = 0; i < 4; i++) {
            int ls = tid + i * 256;
            int row = ls >> 3, cb = (ls & 7) * 16;
            const char* g = (const char*)(Ab + (size_t)(row0 + row) * K + ke) + cb;
            CP16(aBase + SWZ(ls * 16), g);
        }
#pragma unroll
        for (int i = 0; i < 8; i++) {
            int ls = tid + i * 256;
            int row = ls >> 3, cb = (ls & 7) * 16;
            const char* g = (const char*)(Bb + (size_t)(col0 + row) * K + ke) + cb;
            CP16(bBase + SWZ(ls * 16), g);
        }
    }
}

// ---------------- compute chunk + interleaved prefetch --------------------
// The prefetch target may be the next chunk of this tile OR chunk 0 of the
// next work (persistent cross-tile prefetch) — caller passes pointers/coords.
__device__ __forceinline__ void compute_chunk_pf(float (&acc)[4][8][4],
        uint32_t sA, uint32_t sB, int wm, int wn, int lane,
        bool pf, const __nv_bfloat16* __restrict__ Ab,
        const __nv_bfloat16* __restrict__ Bb, int K, int k0n,
        uint32_t pfA, uint32_t pfB, int row0, int col0, int tid) {
#pragma unroll
    for (int ks = 0; ks < 8; ks++) {
        const int sub = ks >> 2, ksl = ks & 3;
        uint32_t aBase = sA + sub * (BM * 128);
        uint32_t bBase = sB + sub * (BN * 128);
        uint32_t a[4][4];
#pragma unroll
        for (int mi = 0; mi < 4; mi++) {
            int row = wm * 64 + mi * 16 + (lane & 15);
            uint32_t off = row * 128 + ksl * 32 + ((lane >> 4) << 4);
            LDSM4(a[mi][0], a[mi][1], a[mi][2], a[mi][3], aBase + SWZ(off));
        }
        uint32_t b[8][2];
#pragma unroll
        for (int nj = 0; nj < 4; nj++) {
            int nrow = wn * 64 + nj * 16 + (lane & 7) + ((lane & 16) >> 1);
            uint32_t off = nrow * 128 + ksl * 32 + (((lane >> 3) & 1) << 4);
            uint32_t r0, r1, r2, r3;
            LDSM4(r0, r1, r2, r3, bBase + SWZ(off));
            b[2 * nj][0] = r0;     b[2 * nj][1] = r1;
            b[2 * nj + 1][0] = r2; b[2 * nj + 1][1] = r3;
        }

        if (pf && ks < 4) {
#pragma unroll
            for (int q = 0; q < 6; q++) {
                const int j = ks * 6 + q;
                const int psub = j / 12, r = j % 12;
                const int ke = k0n + psub * 64;
                if (r < 4) {
                    int ls = tid + r * 256;
                    int row = ls >> 3, cb = (ls & 7) * 16;
                    const char* g = (const char*)(Ab + (size_t)(row0 + row) * K + ke) + cb;
                    CP16(pfA + psub * (BM * 128) + SWZ(ls * 16), g);
                } else {
                    int i = r - 4;
                    int ls = tid + i * 256;
                    int row = ls >> 3, cb = (ls & 7) * 16;
                    const char* g = (const char*)(Bb + (size_t)(col0 + row) * K + ke) + cb;
                    CP16(pfB + psub * (BN * 128) + SWZ(ls * 16), g);
                }
            }
        }

#pragma unroll
        for (int mi = 0; mi < 4; mi++)
#pragma unroll
            for (int ni = 0; ni < 8; ni++)
                MMA16816(acc[mi][ni], a[mi], b[ni]);
    }
    CP_COMMIT();
}

// ---------------- mainloop: 2-stage ring + cross-tile chunk-0 prefetch ------
__device__ __forceinline__ void gemm_mainloop(float (&acc)[4][8][4],
        const __nv_bfloat16* Ab, const __nv_bfloat16* Bb,
        int K, int nch, uint32_t sb, int row0, int col0,
        int tid, int wm, int wn, int lane,
        bool preloaded, bool haveNext,
        const __nv_bfloat16* nAb, const __nv_bfloat16* nBb,
        int nK, int nrow0, int ncol0) {
    if (!preloaded) {
        load_chunk(Ab, Bb, K, 0, 0, sb, row0, col0, tid);
        CP_COMMIT();
    }
    for (int c = 0; c < nch; c++) {
        const int st = c & 1;
        CP_WAIT(0);
        __syncthreads();   // chunk c visible; stage st^1 free (compute c-1 done)

        uint32_t sA = sb + st * STAGE_B;
        uint32_t sB = sA + BM * 256;
        uint32_t oA = sb + (st ^ 1) * STAGE_B;
        uint32_t oB = oA + BM * 256;
        if (c + 1 < nch)
            compute_chunk_pf(acc, sA, sB, wm, wn, lane, true,
                             Ab, Bb, K, (c + 1) * BK, oA, oB, row0, col0, tid);
        else  // last chunk: prefetch chunk 0 of the NEXT work into stage st^1
            compute_chunk_pf(acc, sA, sB, wm, wn, lane, haveNext,
                             nAb, nBb, nK, 0, oA, oB, nrow0, ncol0, tid);
    }
}

// ---------------- persistent S+T GEMM kernel ----------------
// grid = GRID (all co-resident). Work w<NCTA: student tile; else teacher tile.
// Each CTA processes all its S works before its T works (global index order),
// so if every CTA is polling a T flag, all S works are done -> deadlock-free.
__global__ void __launch_bounds__(256, 1)
gemm_persistent_kernel() {
    extern __shared__ __align__(1024) char smem[];
    uint32_t sb = smem_u32(smem);
    const int tid = threadIdx.x, wid = tid >> 5, lane = tid & 31;
    const int wm = wid & 1, wn = wid >> 1;

    bool preloaded = false;
    for (int w = blockIdx.x; w < NWORK; w += GRID) {
        const int phase = (w >= NCTA);
        const int lin = phase ? (w - NCTA) : w;
        const int mt = lin & 31, nt = lin >> 5;
        const int row0 = mt * BM, col0 = nt * BN;
        const __nv_bfloat16* Ab = phase ? g_tin_bf : g_sin_bf;
        const __nv_bfloat16* Bb = phase ? g_tw_bf  : g_sw_bf;
        const int K = phase ? KT : KS;
        const int nch = phase ? NCH_T : NCH_S;

        const int w2 = w + GRID;
        const bool haveNext = (w2 < NWORK);
        const int w2c = haveNext ? w2 : w;              // clamp for safe addressing
        const int phase2 = (w2c >= NCTA);
        const int lin2 = phase2 ? (w2c - NCTA) : w2c;
        const int nrow0 = (lin2 & 31) * BM, ncol0 = (lin2 >> 5) * BN;
        const __nv_bfloat16* nAb = phase2 ? g_tin_bf : g_sin_bf;
        const __nv_bfloat16* nBb = phase2 ? g_tw_bf  : g_sw_bf;
        const int nK = phase2 ? KT : KS;

        float acc[4][8][4];
#pragma unroll
        for (int i = 0; i < 4; i++)
#pragma unroll
            for (int j = 0; j < 8; j++)
#pragma unroll
                for (int k = 0; k < 4; k++) acc[i][j][k] = 0.f;

        gemm_mainloop(acc, Ab, Bb, K, nch, sb, row0, col0, tid, wm, wn, lane,
                      preloaded, haveNext, nAb, nBb, nK, nrow0, ncol0);
        preloaded = haveNext;

        if (!phase) {
            // ---- S epilogue: slog stores, completion flag, per-row partials ----
            size_t base = (size_t)lin * 4096 + tid;
#pragma unroll
            for (int mi = 0; mi < 4; mi++) {
#pragma unroll
                for (int nj = 0; nj < 4; nj++) {
                    uint32_t u[4];
#pragma unroll
                    for (int q = 0; q < 2; q++) {
                        int ni = nj * 2 + q;
                        __nv_bfloat162 p0 = __float22bfloat162_rn(
                            make_float2(acc[mi][ni][0], acc[mi][ni][1]));
                        __nv_bfloat162 p1 = __float22bfloat162_rn(
                            make_float2(acc[mi][ni][2], acc[mi][ni][3]));
                        u[2 * q]     = *reinterpret_cast<uint32_t*>(&p0);
                        u[2 * q + 1] = *reinterpret_cast<uint32_t*>(&p1);
                    }
                    g_slog[base + (size_t)(mi * 4 + nj) * 256] =
                        make_uint4(u[0], u[1], u[2], u[3]);
                }
            }
            __threadfence();
            __syncthreads();
            if (tid == 0) atomicExch(&g_sdone[lin], 1);

#pragma unroll
            for (int mi = 0; mi < 4; mi++) {
#pragma unroll
                for (int h = 0; h < 2; h++) {
                    float s[16];
#pragma unroll
                    for (int ni = 0; ni < 8; ni++) {
                        s[2 * ni]     = acc[mi][ni][h * 2];
                        s[2 * ni + 1] = acc[mi][ni][h * 2 + 1];
                    }
                    float m = s[0];
#pragma unroll
                    for (int j = 1; j < 16; j++) m = fmaxf(m, s[j]);
                    float z = 0.f, ssq = 0.f;
#pragma unroll
                    for (int j = 0; j < 16; j++) {
                        z += __expf(s[j] - m);
                        ssq = fmaf(s[j], s[j], ssq);
                    }
#pragma unroll
                    for (int off = 1; off < 4; off <<= 1) {
                        float om = __shfl_xor_sync(0xffffffffu, m, off);
                        float oz = __shfl_xor_sync(0xffffffffu, z, off);
                        float os = __shfl_xor_sync(0xffffffffu, ssq, off);
                        float nm = fmaxf(m, om);
                        z = z * __expf(m - nm) + oz * __expf(om - nm);
                        m = nm;
                        ssq += os;
                    }
                    if ((lane & 3) == 0) {
                        int row = row0 + wm * 64 + mi * 16 + h * 8 + (lane >> 2);
                        size_t idx = (size_t)row * NPAD + nt * 4 + wn;
                        g_m[idx] = m; g_z[idx] = z; g_ss[idx] = ssq;
                    }
                }
            }
        } else {
            // ---- T epilogue: wait for S tile lin, then dot/tsq ----
            if (tid == 0) {
                while (atomicAdd(&g_sdone[lin], 0) == 0) { }
            }
            __syncthreads();

            size_t base = (size_t)lin * 4096 + tid;
#pragma unroll
            for (int mi = 0; mi < 4; mi++) {
                uint32_t su[16];
#pragma unroll
                for (int nj = 0; nj < 4; nj++) {
                    uint4 v = g_slog[base + (size_t)(mi * 4 + nj) * 256];
                    su[4 * nj] = v.x; su[4 * nj + 1] = v.y;
                    su[4 * nj + 2] = v.z; su[4 * nj + 3] = v.w;
                }
#pragma unroll
                for (int h = 0; h < 2; h++) {
                    float d = 0.f, tsq = 0.f;
#pragma unroll
                    for (int ni = 0; ni < 8; ni++) {
                        uint32_t u = su[ni * 2 + h];
                        float s0 = __uint_as_float(u << 16);
                        float s1 = __uint_as_float(u & 0xffff0000u);
                        float t0 = acc[mi][ni][h * 2];
                        float t1 = acc[mi][ni][h * 2 + 1];
                        d = fmaf(s0, t0, d); d = fmaf(s1, t1, d);
                        tsq = fmaf(t0, t0, tsq); tsq = fmaf(t1, t1, tsq);
                    }
#pragma unroll
                    for (int off = 1; off < 4; off <<= 1) {
                        d   += __shfl_xor_sync(0xffffffffu, d, off);
                        tsq += __shfl_xor_sync(0xffffffffu, tsq, off);
                    }
                    if ((lane & 3) == 0) {
                        int row = row0 + wm * 64 + mi * 16 + h * 8 + (lane >> 2);
                        size_t idx = (size_t)row * NPAD + nt * 4 + wn;
                        g_d[idx] = d; g_tt[idx] = tsq;
                    }
                }
            }
        }
    }
}

// ---------------- K2: per-row combine + exact target logit ----------------
__global__ void combine_kernel(const int* __restrict__ tgt,
                               const float* __restrict__ s_in,
                               const float* __restrict__ s_w)
{
    int gw = (blockIdx.x * blockDim.x + threadIdx.x) >> 5;
    int lane = threadIdx.x & 31;
    if (gw >= BT) return;
    const int row = gw;

    float m = -FLT_MAX, z = 0.f, d = 0.f, ssq = 0.f, tsq = 0.f;
    for (int n = lane; n < NT4; n += 32) {
        size_t idx = (size_t)row * NPAD + n;
        float om = g_m[idx], oz = g_z[idx];
        float nm = fmaxf(m, om);
        z = z * __expf(m - nm) + oz * __expf(om - nm);
        m = nm;
        d += g_d[idx]; ssq += g_ss[idx]; tsq += g_tt[idx];
    }
#pragma unroll
    for (int off = 16; off > 0; off >>= 1) {
        float om = __shfl_xor_sync(0xffffffffu, m, off);
        float oz = __shfl_xor_sync(0xffffffffu, z, off);
        float od = __shfl_xor_sync(0xffffffffu, d, off);
        float os = __shfl_xor_sync(0xffffffffu, ssq, off);
        float ot = __shfl_xor_sync(0xffffffffu, tsq, off);
        float nm = fmaxf(m, om);
        z = z * __expf(m - nm) + oz * __expf(om - nm);
        m = nm;
        d += od; ssq += os; tsq += ot;
    }

    bool is64 = (tgt[1] == -1);            // int64 layout: high word of -100
    int t = is64 ? tgt[2 * row] : tgt[row];

    float ce = 0.f;
    if (t >= 0) {
        float p = 0.f;
        const float* a = s_in + (size_t)row * KS;
        const float* w = s_w + (size_t)t * KS;
        for (int k = lane * 4; k < KS; k += 128) {
            float4 va = *reinterpret_cast<const float4*>(&a[k]);
            float4 vw = *reinterpret_cast<const float4*>(&w[k]);
            p += va.x * vw.x + va.y * vw.y + va.z * vw.z + va.w * vw.w;
        }
#pragma unroll
        for (int off = 16; off > 0; off >>= 1)
            p += __shfl_xor_sync(0xffffffffu, p, off);
        ce = (m + __logf(z)) - p;
    }
    float cs = d / (fmaxf(sqrtf(ssq), 1e-12f) * fmaxf(sqrtf(tsq), 1e-12f));
    if (lane == 0) { g_row[2 * row] = ce; g_row[2 * row + 1] = cs; }
}

// ---------------- K3: final reduction ----------------
__global__ void finalize_kernel(float* __restrict__ out) {
    __shared__ float sce[256], scs[256];
    int tid = threadIdx.x;
    float ce = 0.f, cs = 0.f;
    for (int r = tid; r < BT; r += 256) {
        ce += g_row[2 * r];
        cs += 1.0f - g_row[2 * r + 1];
    }
    sce[tid] = ce; scs[tid] = cs;
    __syncthreads();
    for (int s = 128; s > 0; s >>= 1) {
        if (tid < s) { sce[tid] += sce[tid + s]; scs[tid] += scs[tid + s]; }
        __syncthreads();
    }
    if (tid == 0)
        out[0] = 0.5f * (sce[0] / (float)BT) + 0.25f * (scs[0] / (float)BT);
}

// ---------------- launch ----------------
extern "C" void kernel_launch(void* const* d_in, const int* in_sizes, int n_in,
                              void* d_out, int out_size)
{
    const float* s_in = (const float*)d_in[0];
    const float* t_in = (const float*)d_in[1];
    const float* s_w  = (const float*)d_in[2];
    const float* t_w  = (const float*)d_in[3];
    const int*   tgt  = (const int*)d_in[4];
    float* out = (float*)d_out;

    cudaFuncSetAttribute(gemm_persistent_kernel,
                         cudaFuncAttributeMaxDynamicSharedMemorySize, SMEM_BYTES);

    cvt_all_kernel<<<8192, 256>>>(s_in, t_in, s_w, t_w);

    gemm_persistent_kernel<<<GRID, 256, SMEM_BYTES>>>();

    combine_kernel<<<(BT * 32) / 256, 256>>>(tgt, s_in, s_w);
    finalize_kernel<<<1, 256>>>(out);
}

// round 13
// speedup vs baseline: 1.0609x; 1.0609x over previous
#include <cuda_runtime.h>
#include <cuda_bf16.h>
#include <math.h>
#include <float.h>
#include <stdint.h>

// ---------------- problem constants ----------------
#define BT   4096
#define KS   2048
#define KT   4096
#define VOC  32000
// ---------------- tiling ----------------
#define BM   128
#define BN   256
#define BK   128           // k-chunk (bf16 elems) = 2 x 128B subtiles per row
#define NT   125           // 32000/256 vocab tiles
#define NT4  500           // NT * 4 warp_n slices
#define NPAD 1024
#define NCH_S (KS/BK)      // 16
#define NCH_T (KT/BK)      // 32
#define NST  2
#define STAGE_B (BM*256 + BN*256)      // 96 KB
#define SMEM_BYTES (NST * STAGE_B)     // 192 KB
#define NCTA (32 * NT)                 // 4000

// ---------------- static device scratch ----------------
__device__ __nv_bfloat16 g_sin_bf[(size_t)BT * KS];
__device__ __nv_bfloat16 g_tin_bf[(size_t)BT * KT];
__device__ __nv_bfloat16 g_sw_bf [(size_t)VOC * KS];
__device__ __nv_bfloat16 g_tw_bf [(size_t)VOC * KT];

__device__ uint4 g_slog[(size_t)NCTA * 256 * 16];   // 262 MB: S fragments, reg-layout

__device__ float g_m [(size_t)BT * NPAD];
__device__ float g_z [(size_t)BT * NPAD];
__device__ float g_d [(size_t)BT * NPAD];
__device__ float g_ss[(size_t)BT * NPAD];
__device__ float g_tt[(size_t)BT * NPAD];
__device__ float g_row[BT * 2];

// ---------------- PTX helpers ----------------
__device__ __forceinline__ uint32_t smem_u32(const void* p) {
    uint32_t a;
    asm("{ .reg .u64 t; cvta.to.shared.u64 t, %1; cvt.u32.u64 %0, t; }" : "=r"(a) : "l"(p));
    return a;
}
#define SWZ(o) ((o) ^ (((o) >> 3) & 0x70))

#define CP16(dst, src) \
    asm volatile("cp.async.cg.shared.global [%0], [%1], 16;" :: "r"(dst), "l"(src) : "memory")
#define CP_COMMIT() asm volatile("cp.async.commit_group;" ::: "memory")
#define CP_WAIT(n)  asm volatile("cp.async.wait_group %0;" :: "n"(n) : "memory")

#define LDSM4(r0, r1, r2, r3, a) \
    asm volatile("ldmatrix.sync.aligned.m8n8.x4.shared.b16 {%0,%1,%2,%3}, [%4];" \
        : "=r"(r0), "=r"(r1), "=r"(r2), "=r"(r3) : "r"(a))

#define MMA16816(d, a, b) \
    asm volatile("mma.sync.aligned.m16n8k16.row.col.f32.bf16.bf16.f32 " \
        "{%0,%1,%2,%3}, {%4,%5,%6,%7}, {%8,%9}, {%0,%1,%2,%3};" \
        : "+f"((d)[0]), "+f"((d)[1]), "+f"((d)[2]), "+f"((d)[3]) \
        : "r"((a)[0]), "r"((a)[1]), "r"((a)[2]), "r"((a)[3]), \
          "r"((b)[0]), "r"((b)[1]))

// ---------------- fused fp32 -> bf16 conversion ----------------
#define N_SIN ((size_t)BT * KS)
#define N_TIN ((size_t)BT * KT)
#define N_SW  ((size_t)VOC * KS)
#define N_TW  ((size_t)VOC * KT)
#define N_TOT (N_SIN + N_TIN + N_SW + N_TW)

__global__ void cvt_all_kernel(const float* __restrict__ s_in,
                               const float* __restrict__ t_in,
                               const float* __restrict__ s_w,
                               const float* __restrict__ t_w) {
    size_t i = ((size_t)blockIdx.x * blockDim.x + threadIdx.x) * 4;
    size_t stride = (size_t)gridDim.x * blockDim.x * 4;
    for (; i < N_TOT; i += stride) {
        const float* src; __nv_bfloat16* dst; size_t off;
        if (i < N_SIN)                    { src = s_in; dst = g_sin_bf; off = i; }
        else if (i < N_SIN + N_TIN)       { src = t_in; dst = g_tin_bf; off = i - N_SIN; }
        else if (i < N_SIN + N_TIN + N_SW){ src = s_w;  dst = g_sw_bf;  off = i - N_SIN - N_TIN; }
        else                              { src = t_w;  dst = g_tw_bf;  off = i - N_SIN - N_TIN - N_SW; }
        float4 v = *reinterpret_cast<const float4*>(src + off);
        __nv_bfloat162 a = __float22bfloat162_rn(make_float2(v.x, v.y));
        __nv_bfloat162 b = __float22bfloat162_rn(make_float2(v.z, v.w));
        uint2 o;
        o.x = *reinterpret_cast<uint32_t*>(&a);
        o.y = *reinterpret_cast<uint32_t*>(&b);
        *reinterpret_cast<uint2*>(dst + off) = o;
    }
}

// ---------------- bulk chunk loader (prologue only) ----------------
__device__ __forceinline__ void load_chunk(const __nv_bfloat16* __restrict__ Ab,
                                           const __nv_bfloat16* __restrict__ Bb,
                                           int K, int k0, int st, uint32_t sb,
                                           int row0, int col0, int tid) {
    uint32_t sA = sb + st * STAGE_B;
    uint32_t sB = sA + BM * 256;
#pragma unroll
    for (int sub = 0; sub < 2; sub++) {
        int ke = k0 + sub * 64;
        uint32_t aBase = sA + sub * (BM * 128);
        uint32_t bBase = sB + sub * (BN * 128);
#pragma unroll
        for (int i = 0; i < 4; i++) {
            int ls = tid + i * 256;
            int row = ls >> 3, cb = (ls & 7) * 16;
            const char* g = (const char*)(Ab + (size_t)(row0 + row) * K + ke) + cb;
            CP16(aBase + SWZ(ls * 16), g);
        }
#pragma unroll
        for (int i = 0; i < 8; i++) {
            int ls = tid + i * 256;
            int row = ls >> 3, cb = (ls & 7) * 16;
            const char* g = (const char*)(Bb + (size_t)(col0 + row) * K + ke) + cb;
            CP16(bBase + SWZ(ls * 16), g);
        }
    }
}

// ---------------- compute chunk + interleaved prefetch of next chunk --------
__device__ __forceinline__ void compute_chunk_pf(float (&acc)[4][8][4],
        uint32_t sA, uint32_t sB, int wm, int wn, int lane,
        bool pf, const __nv_bfloat16* __restrict__ Ab,
        const __nv_bfloat16* __restrict__ Bb, int K, int k0n,
        uint32_t pfA, uint32_t pfB, int row0, int col0, int tid) {
#pragma unroll
    for (int ks = 0; ks < 8; ks++) {
        const int sub = ks >> 2, ksl = ks & 3;
        uint32_t aBase = sA + sub * (BM * 128);
        uint32_t bBase = sB + sub * (BN * 128);
        uint32_t a[4][4];
#pragma unroll
        for (int mi = 0; mi < 4; mi++) {
            int row = wm * 64 + mi * 16 + (lane & 15);
            uint32_t off = row * 128 + ksl * 32 + ((lane >> 4) << 4);
            LDSM4(a[mi][0], a[mi][1], a[mi][2], a[mi][3], aBase + SWZ(off));
        }
        uint32_t b[8][2];
#pragma unroll
        for (int nj = 0; nj < 4; nj++) {
            int nrow = wn * 64 + nj * 16 + (lane & 7) + ((lane & 16) >> 1);
            uint32_t off = nrow * 128 + ksl * 32 + (((lane >> 3) & 1) << 4);
            uint32_t r0, r1, r2, r3;
            LDSM4(r0, r1, r2, r3, bBase + SWZ(off));
            b[2 * nj][0] = r0;     b[2 * nj][1] = r1;
            b[2 * nj + 1][0] = r2; b[2 * nj + 1][1] = r3;
        }

        // interleaved prefetch: flat load index j = ks*6+q in [0,24)
        if (pf && ks < 4) {
#pragma unroll
            for (int q = 0; q < 6; q++) {
                const int j = ks * 6 + q;
                const int psub = j / 12, r = j % 12;
                const int ke = k0n + psub * 64;
                if (r < 4) {
                    int ls = tid + r * 256;
                    int row = ls >> 3, cb = (ls & 7) * 16;
                    const char* g = (const char*)(Ab + (size_t)(row0 + row) * K + ke) + cb;
                    CP16(pfA + psub * (BM * 128) + SWZ(ls * 16), g);
                } else {
                    int i = r - 4;
                    int ls = tid + i * 256;
                    int row = ls >> 3, cb = (ls & 7) * 16;
                    const char* g = (const char*)(Bb + (size_t)(col0 + row) * K + ke) + cb;
                    CP16(pfB + psub * (BN * 128) + SWZ(ls * 16), g);
                }
            }
        }

#pragma unroll
        for (int mi = 0; mi < 4; mi++)
#pragma unroll
            for (int ni = 0; ni < 8; ni++)
                MMA16816(acc[mi][ni], a[mi], b[ni]);
    }
    CP_COMMIT();
}

// ---------------- T-last-chunk variant: prefetch g_slog into free stage -----
// Instead of next-chunk tiles, the pf slots copy this tile's 64 KB g_slog
// block into the free stage (linear layout: uint4 slot j, thread tid at
// smem offset (j*256+tid)*16). Thread tid later reads exactly the slots it
// copied -> per-thread self-consistent, CP_WAIT(0) suffices (no barrier).
__device__ __forceinline__ void compute_chunk_slogpf(float (&acc)[4][8][4],
        uint32_t sA, uint32_t sB, int wm, int wn, int lane,
        const uint4* __restrict__ slogSrc, uint32_t dstStage, int tid) {
#pragma unroll
    for (int ks = 0; ks < 8; ks++) {
        const int sub = ks >> 2, ksl = ks & 3;
        uint32_t aBase = sA + sub * (BM * 128);
        uint32_t bBase = sB + sub * (BN * 128);
        uint32_t a[4][4];
#pragma unroll
        for (int mi = 0; mi < 4; mi++) {
            int row = wm * 64 + mi * 16 + (lane & 15);
            uint32_t off = row * 128 + ksl * 32 + ((lane >> 4) << 4);
            LDSM4(a[mi][0], a[mi][1], a[mi][2], a[mi][3], aBase + SWZ(off));
        }
        uint32_t b[8][2];
#pragma unroll
        for (int nj = 0; nj < 4; nj++) {
            int nrow = wn * 64 + nj * 16 + (lane & 7) + ((lane & 16) >> 1);
            uint32_t off = nrow * 128 + ksl * 32 + (((lane >> 3) & 1) << 4);
            uint32_t r0, r1, r2, r3;
            LDSM4(r0, r1, r2, r3, bBase + SWZ(off));
            b[2 * nj][0] = r0;     b[2 * nj][1] = r1;
            b[2 * nj + 1][0] = r2; b[2 * nj + 1][1] = r3;
        }

        if (ks < 4) {   // 4 slog copies per ks-step -> 16 total (64 KB/CTA)
#pragma unroll
            for (int q = 0; q < 4; q++) {
                const int j = ks * 4 + q;
                const char* g = (const char*)(slogSrc + (size_t)j * 256 + tid);
                CP16(dstStage + (uint32_t)(j * 256 + tid) * 16, g);
            }
        }

#pragma unroll
        for (int mi = 0; mi < 4; mi++)
#pragma unroll
            for (int ni = 0; ni < 8; ni++)
                MMA16816(acc[mi][ni], a[mi], b[ni]);
    }
    CP_COMMIT();
}

// ---------------- S mainloop (round-10 proven, unchanged) ----------------
__device__ __forceinline__ void gemm_mainloop(float (&acc)[4][8][4],
                                              const __nv_bfloat16* Ab,
                                              const __nv_bfloat16* Bb,
                                              int K, int nch, uint32_t sb,
                                              int row0, int col0,
                                              int tid, int wm, int wn, int lane) {
    load_chunk(Ab, Bb, K, 0, 0, sb, row0, col0, tid); CP_COMMIT();

    for (int c = 0; c < nch; c++) {
        const int st = c & 1;
        CP_WAIT(0);
        __syncthreads();

        uint32_t sA = sb + st * STAGE_B;
        uint32_t sB = sA + BM * 256;
        uint32_t oA = sb + (st ^ 1) * STAGE_B;
        uint32_t oB = oA + BM * 256;
        compute_chunk_pf(acc, sA, sB, wm, wn, lane,
                         (c + 1 < nch), Ab, Bb, K, (c + 1) * BK,
                         oA, oB, row0, col0, tid);
    }
}

// ---------------- T mainloop: last chunk prefetches g_slog ----------------
__device__ __forceinline__ void gemm_mainloop_T(float (&acc)[4][8][4],
                                                const __nv_bfloat16* Ab,
                                                const __nv_bfloat16* Bb,
                                                uint32_t sb, int row0, int col0,
                                                int tid, int wm, int wn, int lane,
                                                const uint4* slogSrc) {
    load_chunk(Ab, Bb, KT, 0, 0, sb, row0, col0, tid); CP_COMMIT();

    for (int c = 0; c < NCH_T; c++) {
        const int st = c & 1;
        CP_WAIT(0);
        __syncthreads();

        uint32_t sA = sb + st * STAGE_B;
        uint32_t sB = sA + BM * 256;
        uint32_t oA = sb + (st ^ 1) * STAGE_B;
        uint32_t oB = oA + BM * 256;
        if (c + 1 < NCH_T)
            compute_chunk_pf(acc, sA, sB, wm, wn, lane, true,
                             Ab, Bb, KT, (c + 1) * BK, oA, oB, row0, col0, tid);
        else   // last chunk: c=31, st=1 -> free stage 0
            compute_chunk_slogpf(acc, sA, sB, wm, wn, lane, slogSrc, oA, tid);
    }
}

// ---------------- merged S+T GEMM kernel (round-10 structure) ----------------
__global__ void __launch_bounds__(256, 1)
gemm_fused_kernel() {
    extern __shared__ __align__(1024) char smem[];
    uint32_t sb = smem_u32(smem);
    const int tid = threadIdx.x, wid = tid >> 5, lane = tid & 31;
    const int wm = wid & 1, wn = wid >> 1;
    const int bid = blockIdx.x;
    const int phase = (bid >= NCTA);
    const int lin = phase ? (bid - NCTA) : bid;
    const int mt = lin & 31, nt = lin >> 5;
    const int row0 = mt * BM, col0 = nt * BN;
    const int ctaLin = lin;

    float acc[4][8][4];
#pragma unroll
    for (int i = 0; i < 4; i++)
#pragma unroll
        for (int j = 0; j < 8; j++)
#pragma unroll
            for (int k = 0; k < 4; k++) acc[i][j][k] = 0.f;

    if (!phase) {
        // ================= phase S =================
        gemm_mainloop(acc, g_sin_bf, g_sw_bf, KS, NCH_S, sb, row0, col0, tid, wm, wn, lane);

        size_t base = (size_t)ctaLin * 4096 + tid;
#pragma unroll
        for (int mi = 0; mi < 4; mi++) {
#pragma unroll
            for (int nj = 0; nj < 4; nj++) {
                uint32_t u[4];
#pragma unroll
                for (int q = 0; q < 2; q++) {
                    int ni = nj * 2 + q;
                    __nv_bfloat162 p0 = __float22bfloat162_rn(
                        make_float2(acc[mi][ni][0], acc[mi][ni][1]));
                    __nv_bfloat162 p1 = __float22bfloat162_rn(
                        make_float2(acc[mi][ni][2], acc[mi][ni][3]));
                    u[2 * q]     = *reinterpret_cast<uint32_t*>(&p0);
                    u[2 * q + 1] = *reinterpret_cast<uint32_t*>(&p1);
                }
                g_slog[base + (size_t)(mi * 4 + nj) * 256] =
                    make_uint4(u[0], u[1], u[2], u[3]);
            }
        }

#pragma unroll
        for (int mi = 0; mi < 4; mi++) {
#pragma unroll
            for (int h = 0; h < 2; h++) {
                float s[16];
#pragma unroll
                for (int ni = 0; ni < 8; ni++) {
                    s[2 * ni]     = acc[mi][ni][h * 2];
                    s[2 * ni + 1] = acc[mi][ni][h * 2 + 1];
                }
                float m = s[0];
#pragma unroll
                for (int j = 1; j < 16; j++) m = fmaxf(m, s[j]);
                float z = 0.f, ssq = 0.f;
#pragma unroll
                for (int j = 0; j < 16; j++) {
                    z += __expf(s[j] - m);
                    ssq = fmaf(s[j], s[j], ssq);
                }
#pragma unroll
                for (int off = 1; off < 4; off <<= 1) {
                    float om = __shfl_xor_sync(0xffffffffu, m, off);
                    float oz = __shfl_xor_sync(0xffffffffu, z, off);
                    float os = __shfl_xor_sync(0xffffffffu, ssq, off);
                    float nm = fmaxf(m, om);
                    z = z * __expf(m - nm) + oz * __expf(om - nm);
                    m = nm;
                    ssq += os;
                }
                if ((lane & 3) == 0) {
                    int row = row0 + wm * 64 + mi * 16 + h * 8 + (lane >> 2);
                    size_t idx = (size_t)row * NPAD + nt * 4 + wn;
                    g_m[idx] = m; g_z[idx] = z; g_ss[idx] = ssq;
                }
            }
        }
    } else {
        // ================= phase T =================
        const uint4* slogSrc = g_slog + (size_t)ctaLin * 4096;
        gemm_mainloop_T(acc, g_tin_bf, g_tw_bf, sb, row0, col0, tid, wm, wn, lane,
                        slogSrc);

        CP_WAIT(0);   // drain slog copies (per-thread self-consistent: no barrier)
        const uint4* slogSm = reinterpret_cast<const uint4*>(smem);  // stage 0
#pragma unroll
        for (int mi = 0; mi < 4; mi++) {
            uint32_t su[16];
#pragma unroll
            for (int nj = 0; nj < 4; nj++) {
                uint4 v = slogSm[(mi * 4 + nj) * 256 + tid];
                su[4 * nj] = v.x; su[4 * nj + 1] = v.y;
                su[4 * nj + 2] = v.z; su[4 * nj + 3] = v.w;
            }
#pragma unroll
            for (int h = 0; h < 2; h++) {
                float d = 0.f, tsq = 0.f;
#pragma unroll
                for (int ni = 0; ni < 8; ni++) {
                    uint32_t u = su[ni * 2 + h];
                    float s0 = __uint_as_float(u << 16);
                    float s1 = __uint_as_float(u & 0xffff0000u);
                    float t0 = acc[mi][ni][h * 2];
                    float t1 = acc[mi][ni][h * 2 + 1];
                    d = fmaf(s0, t0, d); d = fmaf(s1, t1, d);
                    tsq = fmaf(t0, t0, tsq); tsq = fmaf(t1, t1, tsq);
                }
#pragma unroll
                for (int off = 1; off < 4; off <<= 1) {
                    d   += __shfl_xor_sync(0xffffffffu, d, off);
                    tsq += __shfl_xor_sync(0xffffffffu, tsq, off);
                }
                if ((lane & 3) == 0) {
                    int row = row0 + wm * 64 + mi * 16 + h * 8 + (lane >> 2);
                    size_t idx = (size_t)row * NPAD + nt * 4 + wn;
                    g_d[idx] = d; g_tt[idx] = tsq;
                }
            }
        }
    }
}

// ---------------- K2: per-row combine + exact target logit ----------------
__global__ void combine_kernel(const int* __restrict__ tgt,
                               const float* __restrict__ s_in,
                               const float* __restrict__ s_w)
{
    int gw = (blockIdx.x * blockDim.x + threadIdx.x) >> 5;
    int lane = threadIdx.x & 31;
    if (gw >= BT) return;
    const int row = gw;

    float m = -FLT_MAX, z = 0.f, d = 0.f, ssq = 0.f, tsq = 0.f;
    for (int n = lane; n < NT4; n += 32) {
        size_t idx = (size_t)row * NPAD + n;
        float om = g_m[idx], oz = g_z[idx];
        float nm = fmaxf(m, om);
        z = z * __expf(m - nm) + oz * __expf(om - nm);
        m = nm;
        d += g_d[idx]; ssq += g_ss[idx]; tsq += g_tt[idx];
    }
#pragma unroll
    for (int off = 16; off > 0; off >>= 1) {
        float om = __shfl_xor_sync(0xffffffffu, m, off);
        float oz = __shfl_xor_sync(0xffffffffu, z, off);
        float od = __shfl_xor_sync(0xffffffffu, d, off);
        float os = __shfl_xor_sync(0xffffffffu, ssq, off);
        float ot = __shfl_xor_sync(0xffffffffu, tsq, off);
        float nm = fmaxf(m, om);
        z = z * __expf(m - nm) + oz * __expf(om - nm);
        m = nm;
        d += od; ssq += os; tsq += ot;
    }

    bool is64 = (tgt[1] == -1);            // int64 layout: high word of -100
    int t = is64 ? tgt[2 * row] : tgt[row];

    float ce = 0.f;
    if (t >= 0) {
        float p = 0.f;
        const float* a = s_in + (size_t)row * KS;
        const float* w = s_w + (size_t)t * KS;
        for (int k = lane * 4; k < KS; k += 128) {
            float4 va = *reinterpret_cast<const float4*>(&a[k]);
            float4 vw = *reinterpret_cast<const float4*>(&w[k]);
            p += va.x * vw.x + va.y * vw.y + va.z * vw.z + va.w * vw.w;
        }
#pragma unroll
        for (int off = 16; off > 0; off >>= 1)
            p += __shfl_xor_sync(0xffffffffu, p, off);
        ce = (m + __logf(z)) - p;
    }
    float cs = d / (fmaxf(sqrtf(ssq), 1e-12f) * fmaxf(sqrtf(tsq), 1e-12f));
    if (lane == 0) { g_row[2 * row] = ce; g_row[2 * row + 1] = cs; }
}

// ---------------- K3: final reduction ----------------
__global__ void finalize_kernel(float* __restrict__ out) {
    __shared__ float sce[256], scs[256];
    int tid = threadIdx.x;
    float ce = 0.f, cs = 0.f;
    for (int r = tid; r < BT; r += 256) {
        ce += g_row[2 * r];
        cs += 1.0f - g_row[2 * r + 1];
    }
    sce[tid] = ce; scs[tid] = cs;
    __syncthreads();
    for (int s = 128; s > 0; s >>= 1) {
        if (tid < s) { sce[tid] += sce[tid + s]; scs[tid] += scs[tid + s]; }
        __syncthreads();
    }
    if (tid == 0)
        out[0] = 0.5f * (sce[0] / (float)BT) + 0.25f * (scs[0] / (float)BT);
}

// ---------------- launch ----------------
extern "C" void kernel_launch(void* const* d_in, const int* in_sizes, int n_in,
                              void* d_out, int out_size)
{
    const float* s_in = (const float*)d_in[0];
    const float* t_in = (const float*)d_in[1];
    const float* s_w  = (const float*)d_in[2];
    const float* t_w  = (const float*)d_in[3];
    const int*   tgt  = (const int*)d_in[4];
    float* out = (float*)d_out;

    cudaFuncSetAttribute(gemm_fused_kernel,
                         cudaFuncAttributeMaxDynamicSharedMemorySize, SMEM_BYTES);

    cvt_all_kernel<<<8192, 256>>>(s_in, t_in, s_w, t_w);

    gemm_fused_kernel<<<2 * NCTA, 256, SMEM_BYTES>>>();

    combine_kernel<<<(BT * 32) / 256, 256>>>(tgt, s_in, s_w);
    finalize_kernel<<<1, 256>>>(out);
}

// round 14
// speedup vs baseline: 1.0652x; 1.0041x over previous
#include <cuda_runtime.h>
#include <cuda_bf16.h>
#include <math.h>
#include <float.h>
#include <stdint.h>

// ---------------- problem constants ----------------
#define BT   4096
#define KS   2048
#define KT   4096
#define VOC  32000
// ---------------- tiling ----------------
#define BM   128
#define BN   256
#define BK   128           // k-chunk (bf16 elems) = 2 x 128B subtiles per row
#define NT   125           // 32000/256 vocab tiles
#define NT4  500           // NT * 4 warp_n slices
#define NPAD 1024
#define NCH_S (KS/BK)      // 16
#define NCH_T (KT/BK)      // 32
#define NST  2
#define STAGE_B (BM*256 + BN*256)      // 96 KB
#define SMEM_BYTES (NST * STAGE_B)     // 192 KB
#define NCTA (32 * NT)                 // 4000

// ---------------- static device scratch ----------------
__device__ __nv_bfloat16 g_sin_bf[(size_t)BT * KS];
__device__ __nv_bfloat16 g_tin_bf[(size_t)BT * KT];
__device__ __nv_bfloat16 g_sw_bf [(size_t)VOC * KS];
__device__ __nv_bfloat16 g_tw_bf [(size_t)VOC * KT];

__device__ uint4 g_slog[(size_t)NCTA * 256 * 16];   // 262 MB: S fragments, reg-layout

__device__ float g_m [(size_t)BT * NPAD];
__device__ float g_z [(size_t)BT * NPAD];
__device__ float g_d [(size_t)BT * NPAD];
__device__ float g_ss[(size_t)BT * NPAD];
__device__ float g_tt[(size_t)BT * NPAD];
__device__ float g_row[BT * 2];

// ---------------- PTX helpers ----------------
__device__ __forceinline__ uint32_t smem_u32(const void* p) {
    uint32_t a;
    asm("{ .reg .u64 t; cvta.to.shared.u64 t, %1; cvt.u32.u64 %0, t; }" : "=r"(a) : "l"(p));
    return a;
}
#define SWZ(o) ((o) ^ (((o) >> 3) & 0x70))

#define CP16(dst, src) \
    asm volatile("cp.async.cg.shared.global [%0], [%1], 16;" :: "r"(dst), "l"(src) : "memory")
#define CP_COMMIT() asm volatile("cp.async.commit_group;" ::: "memory")
#define CP_WAIT(n)  asm volatile("cp.async.wait_group %0;" :: "n"(n) : "memory")

#define LDSM4(r0, r1, r2, r3, a) \
    asm volatile("ldmatrix.sync.aligned.m8n8.x4.shared.b16 {%0,%1,%2,%3}, [%4];" \
        : "=r"(r0), "=r"(r1), "=r"(r2), "=r"(r3) : "r"(a))

#define MMA16816(d, a, b) \
    asm volatile("mma.sync.aligned.m16n8k16.row.col.f32.bf16.bf16.f32 " \
        "{%0,%1,%2,%3}, {%4,%5,%6,%7}, {%8,%9}, {%0,%1,%2,%3};" \
        : "+f"((d)[0]), "+f"((d)[1]), "+f"((d)[2]), "+f"((d)[3]) \
        : "r"((a)[0]), "r"((a)[1]), "r"((a)[2]), "r"((a)[3]), \
          "r"((b)[0]), "r"((b)[1]))

// ---------------- fp32 -> bf16 conversion: statically partitioned grid ------
#define N_SIN ((size_t)BT * KS)      // 8388608
#define N_TIN ((size_t)BT * KT)      // 16777216
#define N_SW  ((size_t)VOC * KS)     // 65536000
#define N_TW  ((size_t)VOC * KT)     // 131072000
#define CVT_GRID 8192
// block ranges proportional to sizes: 310 / 620 / 2421 / 4841 (sum = 8192)
#define CVT_B1 310
#define CVT_B2 930
#define CVT_B3 3351

__device__ __forceinline__ void cvt4(const float* __restrict__ src,
                                     __nv_bfloat16* __restrict__ dst, size_t off) {
    float4 v = *reinterpret_cast<const float4*>(src + off);
    __nv_bfloat162 a = __float22bfloat162_rn(make_float2(v.x, v.y));
    __nv_bfloat162 b = __float22bfloat162_rn(make_float2(v.z, v.w));
    uint2 o;
    o.x = *reinterpret_cast<uint32_t*>(&a);
    o.y = *reinterpret_cast<uint32_t*>(&b);
    *reinterpret_cast<uint2*>(dst + off) = o;
}

__global__ void cvt_all_kernel(const float* __restrict__ s_in,
                               const float* __restrict__ t_in,
                               const float* __restrict__ s_w,
                               const float* __restrict__ t_w) {
    const int b = blockIdx.x;
    const float* src; __nv_bfloat16* dst; size_t n; int b0, nb;
    if (b < CVT_B1)      { src = s_in; dst = g_sin_bf; n = N_SIN; b0 = 0;      nb = CVT_B1; }
    else if (b < CVT_B2) { src = t_in; dst = g_tin_bf; n = N_TIN; b0 = CVT_B1; nb = CVT_B2 - CVT_B1; }
    else if (b < CVT_B3) { src = s_w;  dst = g_sw_bf;  n = N_SW;  b0 = CVT_B2; nb = CVT_B3 - CVT_B2; }
    else                 { src = t_w;  dst = g_tw_bf;  n = N_TW;  b0 = CVT_B3; nb = CVT_GRID - CVT_B3; }
    size_t i = ((size_t)(b - b0) * blockDim.x + threadIdx.x) * 4;
    const size_t stride = (size_t)nb * blockDim.x * 4;
    for (; i < n; i += stride) cvt4(src, dst, i);   // branch-free inner loop
}

// ---------------- chunk loader: BK=128 as two 128B-row subtiles ----------------
__device__ __forceinline__ void load_chunk(const __nv_bfloat16* __restrict__ Ab,
                                           const __nv_bfloat16* __restrict__ Bb,
                                           int K, int k0, int st, uint32_t sb,
                                           int row0, int col0, int tid) {
    uint32_t sA = sb + st * STAGE_B;
    uint32_t sB = sA + BM * 256;
#pragma unroll
    for (int sub = 0; sub < 2; sub++) {
        int ke = k0 + sub * 64;
        uint32_t aBase = sA + sub * (BM * 128);
        uint32_t bBase = sB + sub * (BN * 128);
#pragma unroll
        for (int i = 0; i < 4; i++) {
            int ls = tid + i * 256;
            int row = ls >> 3, cb = (ls & 7) * 16;
            const char* g = (const char*)(Ab + (size_t)(row0 + row) * K + ke) + cb;
            CP16(aBase + SWZ(ls * 16), g);
        }
#pragma unroll
        for (int i = 0; i < 8; i++) {
            int ls = tid + i * 256;
            int row = ls >> 3, cb = (ls & 7) * 16;
            const char* g = (const char*)(Bb + (size_t)(col0 + row) * K + ke) + cb;
            CP16(bBase + SWZ(ls * 16), g);
        }
    }
}

// ---------------- compute chunk + interleaved prefetch of next chunk --------
__device__ __forceinline__ void compute_chunk_pf(float (&acc)[4][8][4],
        uint32_t sA, uint32_t sB, int wm, int wn, int lane,
        bool pf, const __nv_bfloat16* __restrict__ Ab,
        const __nv_bfloat16* __restrict__ Bb, int K, int k0n,
        uint32_t pfA, uint32_t pfB, int row0, int col0, int tid) {
#pragma unroll
    for (int ks = 0; ks < 8; ks++) {
        const int sub = ks >> 2, ksl = ks & 3;
        uint32_t aBase = sA + sub * (BM * 128);
        uint32_t bBase = sB + sub * (BN * 128);
        uint32_t a[4][4];
#pragma unroll
        for (int mi = 0; mi < 4; mi++) {
            int row = wm * 64 + mi * 16 + (lane & 15);
            uint32_t off = row * 128 + ksl * 32 + ((lane >> 4) << 4);
            LDSM4(a[mi][0], a[mi][1], a[mi][2], a[mi][3], aBase + SWZ(off));
        }
        uint32_t b[8][2];
#pragma unroll
        for (int nj = 0; nj < 4; nj++) {
            int nrow = wn * 64 + nj * 16 + (lane & 7) + ((lane & 16) >> 1);
            uint32_t off = nrow * 128 + ksl * 32 + (((lane >> 3) & 1) << 4);
            uint32_t r0, r1, r2, r3;
            LDSM4(r0, r1, r2, r3, bBase + SWZ(off));
            b[2 * nj][0] = r0;     b[2 * nj][1] = r1;
            b[2 * nj + 1][0] = r2; b[2 * nj + 1][1] = r3;
        }

        // interleaved prefetch: flat load index j = ks*6+q in [0,24)
        if (pf && ks < 4) {
#pragma unroll
            for (int q = 0; q < 6; q++) {
                const int j = ks * 6 + q;
                const int psub = j / 12, r = j % 12;
                const int ke = k0n + psub * 64;
                if (r < 4) {
                    int ls = tid + r * 256;
                    int row = ls >> 3, cb = (ls & 7) * 16;
                    const char* g = (const char*)(Ab + (size_t)(row0 + row) * K + ke) + cb;
                    CP16(pfA + psub * (BM * 128) + SWZ(ls * 16), g);
                } else {
                    int i = r - 4;
                    int ls = tid + i * 256;
                    int row = ls >> 3, cb = (ls & 7) * 16;
                    const char* g = (const char*)(Bb + (size_t)(col0 + row) * K + ke) + cb;
                    CP16(pfB + psub * (BN * 128) + SWZ(ls * 16), g);
                }
            }
        }

#pragma unroll
        for (int mi = 0; mi < 4; mi++)
#pragma unroll
            for (int ni = 0; ni < 8; ni++)
                MMA16816(acc[mi][ni], a[mi], b[ni]);
    }
    CP_COMMIT();
}

// ---------------- mainloop: 2-stage ring, prefetch folded into compute ------
__device__ __forceinline__ void gemm_mainloop(float (&acc)[4][8][4],
                                              const __nv_bfloat16* Ab,
                                              const __nv_bfloat16* Bb,
                                              int K, int nch, uint32_t sb,
                                              int row0, int col0,
                                              int tid, int wm, int wn, int lane) {
    load_chunk(Ab, Bb, K, 0, 0, sb, row0, col0, tid); CP_COMMIT();

    for (int c = 0; c < nch; c++) {
        const int st = c & 1;
        CP_WAIT(0);
        __syncthreads();   // chunk c visible to all; stage st^1 free (compute c-1 done)

        uint32_t sA = sb + st * STAGE_B;
        uint32_t sB = sA + BM * 256;
        uint32_t oA = sb + (st ^ 1) * STAGE_B;
        uint32_t oB = oA + BM * 256;
        compute_chunk_pf(acc, sA, sB, wm, wn, lane,
                         (c + 1 < nch), Ab, Bb, K, (c + 1) * BK,
                         oA, oB, row0, col0, tid);
    }
}

// ---------------- merged S+T GEMM kernel (round-10 proven) ----------------
// 1D grid of 2*NCTA: bid < NCTA -> student phase, else teacher phase.
// T tile i (bid NCTA+i) depends on S tile i (bid i); in-order dispatch with
// <=148 CTAs in flight guarantees S tile i retired long before bid NCTA+i.
__global__ void __launch_bounds__(256, 1)
gemm_fused_kernel() {
    extern __shared__ __align__(1024) char smem[];
    uint32_t sb = smem_u32(smem);
    const int tid = threadIdx.x, wid = tid >> 5, lane = tid & 31;
    const int wm = wid & 1, wn = wid >> 1;
    const int bid = blockIdx.x;
    const int phase = (bid >= NCTA);
    const int lin = phase ? (bid - NCTA) : bid;
    const int mt = lin & 31, nt = lin >> 5;
    const int row0 = mt * BM, col0 = nt * BN;
    const int ctaLin = lin;

    float acc[4][8][4];
#pragma unroll
    for (int i = 0; i < 4; i++)
#pragma unroll
        for (int j = 0; j < 8; j++)
#pragma unroll
            for (int k = 0; k < 4; k++) acc[i][j][k] = 0.f;

    if (!phase) {
        // ================= phase S =================
        gemm_mainloop(acc, g_sin_bf, g_sw_bf, KS, NCH_S, sb, row0, col0, tid, wm, wn, lane);

        size_t base = (size_t)ctaLin * 4096 + tid;
#pragma unroll
        for (int mi = 0; mi < 4; mi++) {
#pragma unroll
            for (int nj = 0; nj < 4; nj++) {
                uint32_t u[4];
#pragma unroll
                for (int q = 0; q < 2; q++) {
                    int ni = nj * 2 + q;
                    __nv_bfloat162 p0 = __float22bfloat162_rn(
                        make_float2(acc[mi][ni][0], acc[mi][ni][1]));
                    __nv_bfloat162 p1 = __float22bfloat162_rn(
                        make_float2(acc[mi][ni][2], acc[mi][ni][3]));
                    u[2 * q]     = *reinterpret_cast<uint32_t*>(&p0);
                    u[2 * q + 1] = *reinterpret_cast<uint32_t*>(&p1);
                }
                g_slog[base + (size_t)(mi * 4 + nj) * 256] =
                    make_uint4(u[0], u[1], u[2], u[3]);
            }
        }

#pragma unroll
        for (int mi = 0; mi < 4; mi++) {
#pragma unroll
            for (int h = 0; h < 2; h++) {
                float s[16];
#pragma unroll
                for (int ni = 0; ni < 8; ni++) {
                    s[2 * ni]     = acc[mi][ni][h * 2];
                    s[2 * ni + 1] = acc[mi][ni][h * 2 + 1];
                }
                float m = s[0];
#pragma unroll
                for (int j = 1; j < 16; j++) m = fmaxf(m, s[j]);
                float z = 0.f, ssq = 0.f;
#pragma unroll
                for (int j = 0; j < 16; j++) {
                    z += __expf(s[j] - m);
                    ssq = fmaf(s[j], s[j], ssq);
                }
#pragma unroll
                for (int off = 1; off < 4; off <<= 1) {
                    float om = __shfl_xor_sync(0xffffffffu, m, off);
                    float oz = __shfl_xor_sync(0xffffffffu, z, off);
                    float os = __shfl_xor_sync(0xffffffffu, ssq, off);
                    float nm = fmaxf(m, om);
                    z = z * __expf(m - nm) + oz * __expf(om - nm);
                    m = nm;
                    ssq += os;
                }
                if ((lane & 3) == 0) {
                    int row = row0 + wm * 64 + mi * 16 + h * 8 + (lane >> 2);
                    size_t idx = (size_t)row * NPAD + nt * 4 + wn;
                    g_m[idx] = m; g_z[idx] = z; g_ss[idx] = ssq;
                }
            }
        }
    } else {
        // ================= phase T =================
        gemm_mainloop(acc, g_tin_bf, g_tw_bf, KT, NCH_T, sb, row0, col0, tid, wm, wn, lane);

        size_t base = (size_t)ctaLin * 4096 + tid;
#pragma unroll
        for (int mi = 0; mi < 4; mi++) {
            uint32_t su[16];
#pragma unroll
            for (int nj = 0; nj < 4; nj++) {
                uint4 v = g_slog[base + (size_t)(mi * 4 + nj) * 256];
                su[4 * nj] = v.x; su[4 * nj + 1] = v.y;
                su[4 * nj + 2] = v.z; su[4 * nj + 3] = v.w;
            }
#pragma unroll
            for (int h = 0; h < 2; h++) {
                float d = 0.f, tsq = 0.f;
#pragma unroll
                for (int ni = 0; ni < 8; ni++) {
                    uint32_t u = su[ni * 2 + h];
                    float s0 = __uint_as_float(u << 16);
                    float s1 = __uint_as_float(u & 0xffff0000u);
                    float t0 = acc[mi][ni][h * 2];
                    float t1 = acc[mi][ni][h * 2 + 1];
                    d = fmaf(s0, t0, d); d = fmaf(s1, t1, d);
                    tsq = fmaf(t0, t0, tsq); tsq = fmaf(t1, t1, tsq);
                }
#pragma unroll
                for (int off = 1; off < 4; off <<= 1) {
                    d   += __shfl_xor_sync(0xffffffffu, d, off);
                    tsq += __shfl_xor_sync(0xffffffffu, tsq, off);
                }
                if ((lane & 3) == 0) {
                    int row = row0 + wm * 64 + mi * 16 + h * 8 + (lane >> 2);
                    size_t idx = (size_t)row * NPAD + nt * 4 + wn;
                    g_d[idx] = d; g_tt[idx] = tsq;
                }
            }
        }
    }
}

// ---------------- K2: per-row combine + exact target logit ----------------
__global__ void combine_kernel(const int* __restrict__ tgt,
                               const float* __restrict__ s_in,
                               const float* __restrict__ s_w)
{
    int gw = (blockIdx.x * blockDim.x + threadIdx.x) >> 5;
    int lane = threadIdx.x & 31;
    if (gw >= BT) return;
    const int row = gw;

    float m = -FLT_MAX, z = 0.f, d = 0.f, ssq = 0.f, tsq = 0.f;
    for (int n = lane; n < NT4; n += 32) {
        size_t idx = (size_t)row * NPAD + n;
        float om = g_m[idx], oz = g_z[idx];
        float nm = fmaxf(m, om);
        z = z * __expf(m - nm) + oz * __expf(om - nm);
        m = nm;
        d += g_d[idx]; ssq += g_ss[idx]; tsq += g_tt[idx];
    }
#pragma unroll
    for (int off = 16; off > 0; off >>= 1) {
        float om = __shfl_xor_sync(0xffffffffu, m, off);
        float oz = __shfl_xor_sync(0xffffffffu, z, off);
        float od = __shfl_xor_sync(0xffffffffu, d, off);
        float os = __shfl_xor_sync(0xffffffffu, ssq, off);
        float ot = __shfl_xor_sync(0xffffffffu, tsq, off);
        float nm = fmaxf(m, om);
        z = z * __expf(m - nm) + oz * __expf(om - nm);
        m = nm;
        d += od; ssq += os; tsq += ot;
    }

    bool is64 = (tgt[1] == -1);            // int64 layout: high word of -100
    int t = is64 ? tgt[2 * row] : tgt[row];

    float ce = 0.f;
    if (t >= 0) {
        float p = 0.f;
        const float* a = s_in + (size_t)row * KS;
        const float* w = s_w + (size_t)t * KS;
        for (int k = lane * 4; k < KS; k += 128) {
            float4 va = *reinterpret_cast<const float4*>(&a[k]);
            float4 vw = *reinterpret_cast<const float4*>(&w[k]);
            p += va.x * vw.x + va.y * vw.y + va.z * vw.z + va.w * vw.w;
        }
#pragma unroll
        for (int off = 16; off > 0; off >>= 1)
            p += __shfl_xor_sync(0xffffffffu, p, off);
        ce = (m + __logf(z)) - p;
    }
    float cs = d / (fmaxf(sqrtf(ssq), 1e-12f) * fmaxf(sqrtf(tsq), 1e-12f));
    if (lane == 0) { g_row[2 * row] = ce; g_row[2 * row + 1] = cs; }
}

// ---------------- K3: final reduction ----------------
__global__ void finalize_kernel(float* __restrict__ out) {
    __shared__ float sce[256], scs[256];
    int tid = threadIdx.x;
    float ce = 0.f, cs = 0.f;
    for (int r = tid; r < BT; r += 256) {
        ce += g_row[2 * r];
        cs += 1.0f - g_row[2 * r + 1];
    }
    sce[tid] = ce; scs[tid] = cs;
    __syncthreads();
    for (int s = 128; s > 0; s >>= 1) {
        if (tid < s) { sce[tid] += sce[tid + s]; scs[tid] += scs[tid + s]; }
        __syncthreads();
    }
    if (tid == 0)
        out[0] = 0.5f * (sce[0] / (float)BT) + 0.25f * (scs[0] / (float)BT);
}

// ---------------- launch ----------------
extern "C" void kernel_launch(void* const* d_in, const int* in_sizes, int n_in,
                              void* d_out, int out_size)
{
    const float* s_in = (const float*)d_in[0];
    const float* t_in = (const float*)d_in[1];
    const float* s_w  = (const float*)d_in[2];
    const float* t_w  = (const float*)d_in[3];
    const int*   tgt  = (const int*)d_in[4];
    float* out = (float*)d_out;

    cudaFuncSetAttribute(gemm_fused_kernel,
                         cudaFuncAttributeMaxDynamicSharedMemorySize, SMEM_BYTES);

    cvt_all_kernel<<<CVT_GRID, 256>>>(s_in, t_in, s_w, t_w);

    gemm_fused_kernel<<<2 * NCTA, 256, SMEM_BYTES>>>();

    combine_kernel<<<(BT * 32) / 256, 256>>>(tgt, s_in, s_w);
    finalize_kernel<<<1, 256>>>(out);
}

// round 15
// speedup vs baseline: 1.0668x; 1.0015x over previous
#include <cuda_runtime.h>
#include <cuda_bf16.h>
#include <math.h>
#include <float.h>
#include <stdint.h>

// ---------------- problem constants ----------------
#define BT   4096
#define KS   2048
#define KT   4096
#define VOC  32000
// ---------------- tiling ----------------
#define BM   128
#define BN   256
#define BK   128           // k-chunk (bf16 elems) = 2 x 128B subtiles per row
#define NT   125           // 32000/256 vocab tiles
#define NT4  500           // NT * 4 warp_n slices
#define NPAD 1024
#define NCH_S (KS/BK)      // 16
#define NCH_T (KT/BK)      // 32
#define NST  2
#define STAGE_B (BM*256 + BN*256)      // 96 KB
#define SMEM_BYTES (NST * STAGE_B)     // 192 KB
#define NCTA (32 * NT)                 // 4000

// ---------------- static device scratch ----------------
__device__ __nv_bfloat16 g_sin_bf[(size_t)BT * KS];
__device__ __nv_bfloat16 g_tin_bf[(size_t)BT * KT];
__device__ __nv_bfloat16 g_sw_bf [(size_t)VOC * KS];
__device__ __nv_bfloat16 g_tw_bf [(size_t)VOC * KT];

__device__ uint4 g_slog[(size_t)NCTA * 256 * 16];   // 262 MB: S fragments, reg-layout

__device__ float g_m [(size_t)BT * NPAD];
__device__ float g_z [(size_t)BT * NPAD];
__device__ float g_d [(size_t)BT * NPAD];
__device__ float g_ss[(size_t)BT * NPAD];
__device__ float g_tt[(size_t)BT * NPAD];
__device__ float g_row[BT * 2];

// ---------------- PTX helpers ----------------
__device__ __forceinline__ uint32_t smem_u32(const void* p) {
    uint32_t a;
    asm("{ .reg .u64 t; cvta.to.shared.u64 t, %1; cvt.u32.u64 %0, t; }" : "=r"(a) : "l"(p));
    return a;
}
#define SWZ(o) ((o) ^ (((o) >> 3) & 0x70))

#define CP16(dst, src) \
    asm volatile("cp.async.cg.shared.global [%0], [%1], 16;" :: "r"(dst), "l"(src) : "memory")
#define CP_COMMIT() asm volatile("cp.async.commit_group;" ::: "memory")
#define CP_WAIT(n)  asm volatile("cp.async.wait_group %0;" :: "n"(n) : "memory")

#define LDSM4(r0, r1, r2, r3, a) \
    asm volatile("ldmatrix.sync.aligned.m8n8.x4.shared.b16 {%0,%1,%2,%3}, [%4];" \
        : "=r"(r0), "=r"(r1), "=r"(r2), "=r"(r3) : "r"(a))

#define MMA16816(d, a, b) \
    asm volatile("mma.sync.aligned.m16n8k16.row.col.f32.bf16.bf16.f32 " \
        "{%0,%1,%2,%3}, {%4,%5,%6,%7}, {%8,%9}, {%0,%1,%2,%3};" \
        : "+f"((d)[0]), "+f"((d)[1]), "+f"((d)[2]), "+f"((d)[3]) \
        : "r"((a)[0]), "r"((a)[1]), "r"((a)[2]), "r"((a)[3]), \
          "r"((b)[0]), "r"((b)[1]))

// ---------------- fp32 -> bf16 conversion: statically partitioned grid ------
#define N_SIN ((size_t)BT * KS)      // 8388608
#define N_TIN ((size_t)BT * KT)      // 16777216
#define N_SW  ((size_t)VOC * KS)     // 65536000
#define N_TW  ((size_t)VOC * KT)     // 131072000
#define CVT_GRID 8192
#define CVT_B1 310
#define CVT_B2 930
#define CVT_B3 3351

__device__ __forceinline__ void cvt4(const float* __restrict__ src,
                                     __nv_bfloat16* __restrict__ dst, size_t off) {
    float4 v = *reinterpret_cast<const float4*>(src + off);
    __nv_bfloat162 a = __float22bfloat162_rn(make_float2(v.x, v.y));
    __nv_bfloat162 b = __float22bfloat162_rn(make_float2(v.z, v.w));
    uint2 o;
    o.x = *reinterpret_cast<uint32_t*>(&a);
    o.y = *reinterpret_cast<uint32_t*>(&b);
    *reinterpret_cast<uint2*>(dst + off) = o;
}

__global__ void cvt_all_kernel(const float* __restrict__ s_in,
                               const float* __restrict__ t_in,
                               const float* __restrict__ s_w,
                               const float* __restrict__ t_w) {
    const int b = blockIdx.x;
    const float* src; __nv_bfloat16* dst; size_t n; int b0, nb;
    if (b < CVT_B1)      { src = s_in; dst = g_sin_bf; n = N_SIN; b0 = 0;      nb = CVT_B1; }
    else if (b < CVT_B2) { src = t_in; dst = g_tin_bf; n = N_TIN; b0 = CVT_B1; nb = CVT_B2 - CVT_B1; }
    else if (b < CVT_B3) { src = s_w;  dst = g_sw_bf;  n = N_SW;  b0 = CVT_B2; nb = CVT_B3 - CVT_B2; }
    else                 { src = t_w;  dst = g_tw_bf;  n = N_TW;  b0 = CVT_B3; nb = CVT_GRID - CVT_B3; }
    size_t i = ((size_t)(b - b0) * blockDim.x + threadIdx.x) * 4;
    const size_t stride = (size_t)nb * blockDim.x * 4;
    for (; i < n; i += stride) cvt4(src, dst, i);
}

// ---------------- chunk loader: BK=128 as two 128B-row subtiles ----------------
__device__ __forceinline__ void load_chunk(const __nv_bfloat16* __restrict__ Ab,
                                           const __nv_bfloat16* __restrict__ Bb,
                                           int K, int k0, int st, uint32_t sb,
                                           int row0, int col0, int tid) {
    uint32_t sA = sb + st * STAGE_B;
    uint32_t sB = sA + BM * 256;
#pragma unroll
    for (int sub = 0; sub < 2; sub++) {
        int ke = k0 + sub * 64;
        uint32_t aBase = sA + sub * (BM * 128);
        uint32_t bBase = sB + sub * (BN * 128);
#pragma unroll
        for (int i = 0; i < 4; i++) {
            int ls = tid + i * 256;
            int row = ls >> 3, cb = (ls & 7) * 16;
            const char* g = (const char*)(Ab + (size_t)(row0 + row) * K + ke) + cb;
            CP16(aBase + SWZ(ls * 16), g);
        }
#pragma unroll
        for (int i = 0; i < 8; i++) {
            int ls = tid + i * 256;
            int row = ls >> 3, cb = (ls & 7) * 16;
            const char* g = (const char*)(Bb + (size_t)(col0 + row) * K + ke) + cb;
            CP16(bBase + SWZ(ls * 16), g);
        }
    }
}

// ---------------- compute chunk + interleaved prefetch of next chunk --------
__device__ __forceinline__ void compute_chunk_pf(float (&acc)[4][8][4],
        uint32_t sA, uint32_t sB, int wm, int wn, int lane,
        bool pf, const __nv_bfloat16* __restrict__ Ab,
        const __nv_bfloat16* __restrict__ Bb, int K, int k0n,
        uint32_t pfA, uint32_t pfB, int row0, int col0, int tid) {
#pragma unroll
    for (int ks = 0; ks < 8; ks++) {
        const int sub = ks >> 2, ksl = ks & 3;
        uint32_t aBase = sA + sub * (BM * 128);
        uint32_t bBase = sB + sub * (BN * 128);
        uint32_t a[4][4];
#pragma unroll
        for (int mi = 0; mi < 4; mi++) {
            int row = wm * 64 + mi * 16 + (lane & 15);
            uint32_t off = row * 128 + ksl * 32 + ((lane >> 4) << 4);
            LDSM4(a[mi][0], a[mi][1], a[mi][2], a[mi][3], aBase + SWZ(off));
        }
        uint32_t b[8][2];
#pragma unroll
        for (int nj = 0; nj < 4; nj++) {
            int nrow = wn * 64 + nj * 16 + (lane & 7) + ((lane & 16) >> 1);
            uint32_t off = nrow * 128 + ksl * 32 + (((lane >> 3) & 1) << 4);
            uint32_t r0, r1, r2, r3;
            LDSM4(r0, r1, r2, r3, bBase + SWZ(off));
            b[2 * nj][0] = r0;     b[2 * nj][1] = r1;
            b[2 * nj + 1][0] = r2; b[2 * nj + 1][1] = r3;
        }

        // interleaved prefetch: flat load index j = ks*6+q in [0,24)
        if (pf && ks < 4) {
#pragma unroll
            for (int q = 0; q < 6; q++) {
                const int j = ks * 6 + q;
                const int psub = j / 12, r = j % 12;
                const int ke = k0n + psub * 64;
                if (r < 4) {
                    int ls = tid + r * 256;
                    int row = ls >> 3, cb = (ls & 7) * 16;
                    const char* g = (const char*)(Ab + (size_t)(row0 + row) * K + ke) + cb;
                    CP16(pfA + psub * (BM * 128) + SWZ(ls * 16), g);
                } else {
                    int i = r - 4;
                    int ls = tid + i * 256;
                    int row = ls >> 3, cb = (ls & 7) * 16;
                    const char* g = (const char*)(Bb + (size_t)(col0 + row) * K + ke) + cb;
                    CP16(pfB + psub * (BN * 128) + SWZ(ls * 16), g);
                }
            }
        }

#pragma unroll
        for (int mi = 0; mi < 4; mi++)
#pragma unroll
            for (int ni = 0; ni < 8; ni++)
                MMA16816(acc[mi][ni], a[mi], b[ni]);
    }
    CP_COMMIT();
}

// ---------------- mainloop: 2-stage ring, prefetch folded into compute ------
__device__ __forceinline__ void gemm_mainloop(float (&acc)[4][8][4],
                                              const __nv_bfloat16* Ab,
                                              const __nv_bfloat16* Bb,
                                              int K, int nch, uint32_t sb,
                                              int row0, int col0,
                                              int tid, int wm, int wn, int lane) {
    load_chunk(Ab, Bb, K, 0, 0, sb, row0, col0, tid); CP_COMMIT();

    for (int c = 0; c < nch; c++) {
        const int st = c & 1;
        CP_WAIT(0);
        __syncthreads();

        uint32_t sA = sb + st * STAGE_B;
        uint32_t sB = sA + BM * 256;
        uint32_t oA = sb + (st ^ 1) * STAGE_B;
        uint32_t oB = oA + BM * 256;
        compute_chunk_pf(acc, sA, sB, wm, wn, lane,
                         (c + 1 < nch), Ab, Bb, K, (c + 1) * BK,
                         oA, oB, row0, col0, tid);
    }
}

// ---------------- merged S+T GEMM kernel (round-10 proven) ----------------
__global__ void __launch_bounds__(256, 1)
gemm_fused_kernel() {
    extern __shared__ __align__(1024) char smem[];
    uint32_t sb = smem_u32(smem);
    const int tid = threadIdx.x, wid = tid >> 5, lane = tid & 31;
    const int wm = wid & 1, wn = wid >> 1;
    const int bid = blockIdx.x;
    const int phase = (bid >= NCTA);
    const int lin = phase ? (bid - NCTA) : bid;
    const int mt = lin & 31, nt = lin >> 5;
    const int row0 = mt * BM, col0 = nt * BN;
    const int ctaLin = lin;

    float acc[4][8][4];
#pragma unroll
    for (int i = 0; i < 4; i++)
#pragma unroll
        for (int j = 0; j < 8; j++)
#pragma unroll
            for (int k = 0; k < 4; k++) acc[i][j][k] = 0.f;

    if (!phase) {
        // ================= phase S =================
        gemm_mainloop(acc, g_sin_bf, g_sw_bf, KS, NCH_S, sb, row0, col0, tid, wm, wn, lane);

        size_t base = (size_t)ctaLin * 4096 + tid;
#pragma unroll
        for (int mi = 0; mi < 4; mi++) {
#pragma unroll
            for (int nj = 0; nj < 4; nj++) {
                uint32_t u[4];
#pragma unroll
                for (int q = 0; q < 2; q++) {
                    int ni = nj * 2 + q;
                    __nv_bfloat162 p0 = __float22bfloat162_rn(
                        make_float2(acc[mi][ni][0], acc[mi][ni][1]));
                    __nv_bfloat162 p1 = __float22bfloat162_rn(
                        make_float2(acc[mi][ni][2], acc[mi][ni][3]));
                    u[2 * q]     = *reinterpret_cast<uint32_t*>(&p0);
                    u[2 * q + 1] = *reinterpret_cast<uint32_t*>(&p1);
                }
                g_slog[base + (size_t)(mi * 4 + nj) * 256] =
                    make_uint4(u[0], u[1], u[2], u[3]);
            }
        }

#pragma unroll
        for (int mi = 0; mi < 4; mi++) {
#pragma unroll
            for (int h = 0; h < 2; h++) {
                float s[16];
#pragma unroll
                for (int ni = 0; ni < 8; ni++) {
                    s[2 * ni]     = acc[mi][ni][h * 2];
                    s[2 * ni + 1] = acc[mi][ni][h * 2 + 1];
                }
                float m = s[0];
#pragma unroll
                for (int j = 1; j < 16; j++) m = fmaxf(m, s[j]);
                float z = 0.f, ssq = 0.f;
#pragma unroll
                for (int j = 0; j < 16; j++) {
                    z += __expf(s[j] - m);
                    ssq = fmaf(s[j], s[j], ssq);
                }
#pragma unroll
                for (int off = 1; off < 4; off <<= 1) {
                    float om = __shfl_xor_sync(0xffffffffu, m, off);
                    float oz = __shfl_xor_sync(0xffffffffu, z, off);
                    float os = __shfl_xor_sync(0xffffffffu, ssq, off);
                    float nm = fmaxf(m, om);
                    z = z * __expf(m - nm) + oz * __expf(om - nm);
                    m = nm;
                    ssq += os;
                }
                if ((lane & 3) == 0) {
                    int row = row0 + wm * 64 + mi * 16 + h * 8 + (lane >> 2);
                    size_t idx = (size_t)row * NPAD + nt * 4 + wn;
                    g_m[idx] = m; g_z[idx] = z; g_ss[idx] = ssq;
                }
            }
        }
    } else {
        // ================= phase T =================
        gemm_mainloop(acc, g_tin_bf, g_tw_bf, KT, NCH_T, sb, row0, col0, tid, wm, wn, lane);

        size_t base = (size_t)ctaLin * 4096 + tid;
#pragma unroll
        for (int mi = 0; mi < 4; mi++) {
            uint32_t su[16];
#pragma unroll
            for (int nj = 0; nj < 4; nj++) {
                uint4 v = g_slog[base + (size_t)(mi * 4 + nj) * 256];
                su[4 * nj] = v.x; su[4 * nj + 1] = v.y;
                su[4 * nj + 2] = v.z; su[4 * nj + 3] = v.w;
            }
#pragma unroll
            for (int h = 0; h < 2; h++) {
                float d = 0.f, tsq = 0.f;
#pragma unroll
                for (int ni = 0; ni < 8; ni++) {
                    uint32_t u = su[ni * 2 + h];
                    float s0 = __uint_as_float(u << 16);
                    float s1 = __uint_as_float(u & 0xffff0000u);
                    float t0 = acc[mi][ni][h * 2];
                    float t1 = acc[mi][ni][h * 2 + 1];
                    d = fmaf(s0, t0, d); d = fmaf(s1, t1, d);
                    tsq = fmaf(t0, t0, tsq); tsq = fmaf(t1, t1, tsq);
                }
#pragma unroll
                for (int off = 1; off < 4; off <<= 1) {
                    d   += __shfl_xor_sync(0xffffffffu, d, off);
                    tsq += __shfl_xor_sync(0xffffffffu, tsq, off);
                }
                if ((lane & 3) == 0) {
                    int row = row0 + wm * 64 + mi * 16 + h * 8 + (lane >> 2);
                    size_t idx = (size_t)row * NPAD + nt * 4 + wn;
                    g_d[idx] = d; g_tt[idx] = tsq;
                }
            }
        }
    }
}

// ---------------- K2: per-row combine, de-serialized (2-phase logsumexp) ----
// All 500 partials are final -> no need for online rescaling. Pass 1 caches
// m/z into register arrays while summing the independent d/ss/tt streams at
// full MLP; then a dependence-free max pass and an independent exp pass.
#define CITER 16   // ceil(NT4 / 32)

__global__ void combine_kernel(const int* __restrict__ tgt,
                               const float* __restrict__ s_in,
                               const float* __restrict__ s_w)
{
    int gw = (blockIdx.x * blockDim.x + threadIdx.x) >> 5;
    int lane = threadIdx.x & 31;
    if (gw >= BT) return;
    const int row = gw;

    float om[CITER], oz[CITER];
    float d = 0.f, ssq = 0.f, tsq = 0.f;
#pragma unroll
    for (int k = 0; k < CITER; k++) {
        int n = lane + k * 32;
        bool v = (n < NT4);
        size_t idx = (size_t)row * NPAD + n;
        om[k] = v ? g_m[idx] : -FLT_MAX;
        oz[k] = v ? g_z[idx] : 0.f;
        if (v) {
            d   += g_d[idx];
            ssq += g_ss[idx];
            tsq += g_tt[idx];
        }
    }
    float m = om[0];
#pragma unroll
    for (int k = 1; k < CITER; k++) m = fmaxf(m, om[k]);
#pragma unroll
    for (int off = 16; off > 0; off >>= 1)
        m = fmaxf(m, __shfl_xor_sync(0xffffffffu, m, off));
    float z = 0.f;
#pragma unroll
    for (int k = 0; k < CITER; k++)
        z += oz[k] * __expf(om[k] - m);     // independent exps, full issue
#pragma unroll
    for (int off = 16; off > 0; off >>= 1) {
        z   += __shfl_xor_sync(0xffffffffu, z, off);
        d   += __shfl_xor_sync(0xffffffffu, d, off);
        ssq += __shfl_xor_sync(0xffffffffu, ssq, off);
        tsq += __shfl_xor_sync(0xffffffffu, tsq, off);
    }

    bool is64 = (tgt[1] == -1);            // int64 layout: high word of -100
    int t = is64 ? tgt[2 * row] : tgt[row];

    float ce = 0.f;
    if (t >= 0) {
        float p = 0.f;
        const float* a = s_in + (size_t)row * KS;
        const float* w = s_w + (size_t)t * KS;
        for (int k = lane * 4; k < KS; k += 128) {
            float4 va = *reinterpret_cast<const float4*>(&a[k]);
            float4 vw = *reinterpret_cast<const float4*>(&w[k]);
            p += va.x * vw.x + va.y * vw.y + va.z * vw.z + va.w * vw.w;
        }
#pragma unroll
        for (int off = 16; off > 0; off >>= 1)
            p += __shfl_xor_sync(0xffffffffu, p, off);
        ce = (m + __logf(z)) - p;
    }
    float cs = d / (fmaxf(sqrtf(ssq), 1e-12f) * fmaxf(sqrtf(tsq), 1e-12f));
    if (lane == 0) { g_row[2 * row] = ce; g_row[2 * row + 1] = cs; }
}

// ---------------- K3: final reduction ----------------
__global__ void finalize_kernel(float* __restrict__ out) {
    __shared__ float sce[256], scs[256];
    int tid = threadIdx.x;
    float ce = 0.f, cs = 0.f;
    for (int r = tid; r < BT; r += 256) {
        ce += g_row[2 * r];
        cs += 1.0f - g_row[2 * r + 1];
    }
    sce[tid] = ce; scs[tid] = cs;
    __syncthreads();
    for (int s = 128; s > 0; s >>= 1) {
        if (tid < s) { sce[tid] += sce[tid + s]; scs[tid] += scs[tid + s]; }
        __syncthreads();
    }
    if (tid == 0)
        out[0] = 0.5f * (sce[0] / (float)BT) + 0.25f * (scs[0] / (float)BT);
}

// ---------------- launch ----------------
extern "C" void kernel_launch(void* const* d_in, const int* in_sizes, int n_in,
                              void* d_out, int out_size)
{
    const float* s_in = (const float*)d_in[0];
    const float* t_in = (const float*)d_in[1];
    const float* s_w  = (const float*)d_in[2];
    const float* t_w  = (const float*)d_in[3];
    const int*   tgt  = (const int*)d_in[4];
    float* out = (float*)d_out;

    cudaFuncSetAttribute(gemm_fused_kernel,
                         cudaFuncAttributeMaxDynamicSharedMemorySize, SMEM_BYTES);

    cvt_all_kernel<<<CVT_GRID, 256>>>(s_in, t_in, s_w, t_w);

    gemm_fused_kernel<<<2 * NCTA, 256, SMEM_BYTES>>>();

    combine_kernel<<<(BT * 32) / 256, 256>>>(tgt, s_in, s_w);
    finalize_kernel<<<1, 256>>>(out);
}

// round 16
// speedup vs baseline: 1.0674x; 1.0005x over previous
#include <cuda_runtime.h>
#include <cuda_bf16.h>
#include <math.h>
#include <float.h>
#include <stdint.h>

// ---------------- problem constants ----------------
#define BT   4096
#define KS   2048
#define KT   4096
#define VOC  32000
// ---------------- tiling ----------------
#define BM   128
#define BN   256
#define BK   128           // k-chunk (bf16 elems) = 2 x 128B subtiles per row
#define NT   125           // 32000/256 vocab tiles
#define NT4  500           // NT * 4 warp_n slices
#define NPAD 1024
#define NCH_S (KS/BK)      // 16
#define NCH_T (KT/BK)      // 32
#define NST  2
#define STAGE_B (BM*256 + BN*256)      // 96 KB
#define SMEM_BYTES (NST * STAGE_B)     // 192 KB
#define NCTA (32 * NT)                 // 4000
#define NCOMB 512                      // combine grid

// ---------------- static device scratch ----------------
__device__ __nv_bfloat16 g_sin_bf[(size_t)BT * KS];
__device__ __nv_bfloat16 g_tin_bf[(size_t)BT * KT];
__device__ __nv_bfloat16 g_sw_bf [(size_t)VOC * KS];
__device__ __nv_bfloat16 g_tw_bf [(size_t)VOC * KT];

__device__ uint4 g_slog[(size_t)NCTA * 256 * 16];   // 262 MB: S fragments, reg-layout

__device__ float g_m [(size_t)BT * NPAD];
__device__ float g_z [(size_t)BT * NPAD];
__device__ float g_d [(size_t)BT * NPAD];
__device__ float g_ss[(size_t)BT * NPAD];
__device__ float g_tt[(size_t)BT * NPAD];
__device__ float g_row[BT * 2];
__device__ int   g_cdone;              // last-block counter for fused finalize

// ---------------- PTX helpers ----------------
__device__ __forceinline__ uint32_t smem_u32(const void* p) {
    uint32_t a;
    asm("{ .reg .u64 t; cvta.to.shared.u64 t, %1; cvt.u32.u64 %0, t; }" : "=r"(a) : "l"(p));
    return a;
}
#define SWZ(o) ((o) ^ (((o) >> 3) & 0x70))

#define CP16(dst, src) \
    asm volatile("cp.async.cg.shared.global [%0], [%1], 16;" :: "r"(dst), "l"(src) : "memory")
#define CP_COMMIT() asm volatile("cp.async.commit_group;" ::: "memory")
#define CP_WAIT(n)  asm volatile("cp.async.wait_group %0;" :: "n"(n) : "memory")

#define LDSM4(r0, r1, r2, r3, a) \
    asm volatile("ldmatrix.sync.aligned.m8n8.x4.shared.b16 {%0,%1,%2,%3}, [%4];" \
        : "=r"(r0), "=r"(r1), "=r"(r2), "=r"(r3) : "r"(a))

#define MMA16816(d, a, b) \
    asm volatile("mma.sync.aligned.m16n8k16.row.col.f32.bf16.bf16.f32 " \
        "{%0,%1,%2,%3}, {%4,%5,%6,%7}, {%8,%9}, {%0,%1,%2,%3};" \
        : "+f"((d)[0]), "+f"((d)[1]), "+f"((d)[2]), "+f"((d)[3]) \
        : "r"((a)[0]), "r"((a)[1]), "r"((a)[2]), "r"((a)[3]), \
          "r"((b)[0]), "r"((b)[1]))

// ---------------- fp32 -> bf16 conversion: statically partitioned grid ------
#define N_SIN ((size_t)BT * KS)      // 8388608
#define N_TIN ((size_t)BT * KT)      // 16777216
#define N_SW  ((size_t)VOC * KS)     // 65536000
#define N_TW  ((size_t)VOC * KT)     // 131072000
#define CVT_GRID 8192
#define CVT_B1 310
#define CVT_B2 930
#define CVT_B3 3351

__device__ __forceinline__ void cvt4(const float* __restrict__ src,
                                     __nv_bfloat16* __restrict__ dst, size_t off) {
    float4 v = *reinterpret_cast<const float4*>(src + off);
    __nv_bfloat162 a = __float22bfloat162_rn(make_float2(v.x, v.y));
    __nv_bfloat162 b = __float22bfloat162_rn(make_float2(v.z, v.w));
    uint2 o;
    o.x = *reinterpret_cast<uint32_t*>(&a);
    o.y = *reinterpret_cast<uint32_t*>(&b);
    *reinterpret_cast<uint2*>(dst + off) = o;
}

__global__ void cvt_all_kernel(const float* __restrict__ s_in,
                               const float* __restrict__ t_in,
                               const float* __restrict__ s_w,
                               const float* __restrict__ t_w) {
    if (blockIdx.x == 0 && threadIdx.x == 0) g_cdone = 0;  // reset per replay
    const int b = blockIdx.x;
    const float* src; __nv_bfloat16* dst; size_t n; int b0, nb;
    if (b < CVT_B1)      { src = s_in; dst = g_sin_bf; n = N_SIN; b0 = 0;      nb = CVT_B1; }
    else if (b < CVT_B2) { src = t_in; dst = g_tin_bf; n = N_TIN; b0 = CVT_B1; nb = CVT_B2 - CVT_B1; }
    else if (b < CVT_B3) { src = s_w;  dst = g_sw_bf;  n = N_SW;  b0 = CVT_B2; nb = CVT_B3 - CVT_B2; }
    else                 { src = t_w;  dst = g_tw_bf;  n = N_TW;  b0 = CVT_B3; nb = CVT_GRID - CVT_B3; }
    size_t i = ((size_t)(b - b0) * blockDim.x + threadIdx.x) * 4;
    const size_t stride = (size_t)nb * blockDim.x * 4;
    for (; i < n; i += stride) cvt4(src, dst, i);
}

// ---------------- chunk loader: BK=128 as two 128B-row subtiles ----------------
__device__ __forceinline__ void load_chunk(const __nv_bfloat16* __restrict__ Ab,
                                           const __nv_bfloat16* __restrict__ Bb,
                                           int K, int k0, int st, uint32_t sb,
                                           int row0, int col0, int tid) {
    uint32_t sA = sb + st * STAGE_B;
    uint32_t sB = sA + BM * 256;
#pragma unroll
    for (int sub = 0; sub < 2; sub++) {
        int ke = k0 + sub * 64;
        uint32_t aBase = sA + sub * (BM * 128);
        uint32_t bBase = sB + sub * (BN * 128);
#pragma unroll
        for (int i = 0; i < 4; i++) {
            int ls = tid + i * 256;
            int row = ls >> 3, cb = (ls & 7) * 16;
            const char* g = (const char*)(Ab + (size_t)(row0 + row) * K + ke) + cb;
            CP16(aBase + SWZ(ls * 16), g);
        }
#pragma unroll
        for (int i = 0; i < 8; i++) {
            int ls = tid + i * 256;
            int row = ls >> 3, cb = (ls & 7) * 16;
            const char* g = (const char*)(Bb + (size_t)(col0 + row) * K + ke) + cb;
            CP16(bBase + SWZ(ls * 16), g);
        }
    }
}

// ---------------- compute chunk + interleaved prefetch of next chunk --------
__device__ __forceinline__ void compute_chunk_pf(float (&acc)[4][8][4],
        uint32_t sA, uint32_t sB, int wm, int wn, int lane,
        bool pf, const __nv_bfloat16* __restrict__ Ab,
        const __nv_bfloat16* __restrict__ Bb, int K, int k0n,
        uint32_t pfA, uint32_t pfB, int row0, int col0, int tid) {
#pragma unroll
    for (int ks = 0; ks < 8; ks++) {
        const int sub = ks >> 2, ksl = ks & 3;
        uint32_t aBase = sA + sub * (BM * 128);
        uint32_t bBase = sB + sub * (BN * 128);
        uint32_t a[4][4];
#pragma unroll
        for (int mi = 0; mi < 4; mi++) {
            int row = wm * 64 + mi * 16 + (lane & 15);
            uint32_t off = row * 128 + ksl * 32 + ((lane >> 4) << 4);
            LDSM4(a[mi][0], a[mi][1], a[mi][2], a[mi][3], aBase + SWZ(off));
        }
        uint32_t b[8][2];
#pragma unroll
        for (int nj = 0; nj < 4; nj++) {
            int nrow = wn * 64 + nj * 16 + (lane & 7) + ((lane & 16) >> 1);
            uint32_t off = nrow * 128 + ksl * 32 + (((lane >> 3) & 1) << 4);
            uint32_t r0, r1, r2, r3;
            LDSM4(r0, r1, r2, r3, bBase + SWZ(off));
            b[2 * nj][0] = r0;     b[2 * nj][1] = r1;
            b[2 * nj + 1][0] = r2; b[2 * nj + 1][1] = r3;
        }

        // interleaved prefetch: flat load index j = ks*6+q in [0,24)
        if (pf && ks < 4) {
#pragma unroll
            for (int q = 0; q < 6; q++) {
                const int j = ks * 6 + q;
                const int psub = j / 12, r = j % 12;
                const int ke = k0n + psub * 64;
                if (r < 4) {
                    int ls = tid + r * 256;
                    int row = ls >> 3, cb = (ls & 7) * 16;
                    const char* g = (const char*)(Ab + (size_t)(row0 + row) * K + ke) + cb;
                    CP16(pfA + psub * (BM * 128) + SWZ(ls * 16), g);
                } else {
                    int i = r - 4;
                    int ls = tid + i * 256;
                    int row = ls >> 3, cb = (ls & 7) * 16;
                    const char* g = (const char*)(Bb + (size_t)(col0 + row) * K + ke) + cb;
                    CP16(pfB + psub * (BN * 128) + SWZ(ls * 16), g);
                }
            }
        }

#pragma unroll
        for (int mi = 0; mi < 4; mi++)
#pragma unroll
            for (int ni = 0; ni < 8; ni++)
                MMA16816(acc[mi][ni], a[mi], b[ni]);
    }
    CP_COMMIT();
}

// ---------------- mainloop: 2-stage ring, prefetch folded into compute ------
__device__ __forceinline__ void gemm_mainloop(float (&acc)[4][8][4],
                                              const __nv_bfloat16* Ab,
                                              const __nv_bfloat16* Bb,
                                              int K, int nch, uint32_t sb,
                                              int row0, int col0,
                                              int tid, int wm, int wn, int lane) {
    load_chunk(Ab, Bb, K, 0, 0, sb, row0, col0, tid); CP_COMMIT();

    for (int c = 0; c < nch; c++) {
        const int st = c & 1;
        CP_WAIT(0);
        __syncthreads();

        uint32_t sA = sb + st * STAGE_B;
        uint32_t sB = sA + BM * 256;
        uint32_t oA = sb + (st ^ 1) * STAGE_B;
        uint32_t oB = oA + BM * 256;
        compute_chunk_pf(acc, sA, sB, wm, wn, lane,
                         (c + 1 < nch), Ab, Bb, K, (c + 1) * BK,
                         oA, oB, row0, col0, tid);
    }
}

// ---------------- merged S+T GEMM kernel (round-10 proven) ----------------
__global__ void __launch_bounds__(256, 1)
gemm_fused_kernel() {
    extern __shared__ __align__(1024) char smem[];
    uint32_t sb = smem_u32(smem);
    const int tid = threadIdx.x, wid = tid >> 5, lane = tid & 31;
    const int wm = wid & 1, wn = wid >> 1;
    const int bid = blockIdx.x;
    const int phase = (bid >= NCTA);
    const int lin = phase ? (bid - NCTA) : bid;
    const int mt = lin & 31, nt = lin >> 5;
    const int row0 = mt * BM, col0 = nt * BN;
    const int ctaLin = lin;

    float acc[4][8][4];
#pragma unroll
    for (int i = 0; i < 4; i++)
#pragma unroll
        for (int j = 0; j < 8; j++)
#pragma unroll
            for (int k = 0; k < 4; k++) acc[i][j][k] = 0.f;

    if (!phase) {
        // ================= phase S =================
        gemm_mainloop(acc, g_sin_bf, g_sw_bf, KS, NCH_S, sb, row0, col0, tid, wm, wn, lane);

        size_t base = (size_t)ctaLin * 4096 + tid;
#pragma unroll
        for (int mi = 0; mi < 4; mi++) {
#pragma unroll
            for (int nj = 0; nj < 4; nj++) {
                uint32_t u[4];
#pragma unroll
                for (int q = 0; q < 2; q++) {
                    int ni = nj * 2 + q;
                    __nv_bfloat162 p0 = __float22bfloat162_rn(
                        make_float2(acc[mi][ni][0], acc[mi][ni][1]));
                    __nv_bfloat162 p1 = __float22bfloat162_rn(
                        make_float2(acc[mi][ni][2], acc[mi][ni][3]));
                    u[2 * q]     = *reinterpret_cast<uint32_t*>(&p0);
                    u[2 * q + 1] = *reinterpret_cast<uint32_t*>(&p1);
                }
                g_slog[base + (size_t)(mi * 4 + nj) * 256] =
                    make_uint4(u[0], u[1], u[2], u[3]);
            }
        }

#pragma unroll
        for (int mi = 0; mi < 4; mi++) {
#pragma unroll
            for (int h = 0; h < 2; h++) {
                float s[16];
#pragma unroll
                for (int ni = 0; ni < 8; ni++) {
                    s[2 * ni]     = acc[mi][ni][h * 2];
                    s[2 * ni + 1] = acc[mi][ni][h * 2 + 1];
                }
                float m = s[0];
#pragma unroll
                for (int j = 1; j < 16; j++) m = fmaxf(m, s[j]);
                float z = 0.f, ssq = 0.f;
#pragma unroll
                for (int j = 0; j < 16; j++) {
                    z += __expf(s[j] - m);
                    ssq = fmaf(s[j], s[j], ssq);
                }
#pragma unroll
                for (int off = 1; off < 4; off <<= 1) {
                    float om = __shfl_xor_sync(0xffffffffu, m, off);
                    float oz = __shfl_xor_sync(0xffffffffu, z, off);
                    float os = __shfl_xor_sync(0xffffffffu, ssq, off);
                    float nm = fmaxf(m, om);
                    z = z * __expf(m - nm) + oz * __expf(om - nm);
                    m = nm;
                    ssq += os;
                }
                if ((lane & 3) == 0) {
                    int row = row0 + wm * 64 + mi * 16 + h * 8 + (lane >> 2);
                    size_t idx = (size_t)row * NPAD + nt * 4 + wn;
                    g_m[idx] = m; g_z[idx] = z; g_ss[idx] = ssq;
                }
            }
        }
    } else {
        // ================= phase T =================
        gemm_mainloop(acc, g_tin_bf, g_tw_bf, KT, NCH_T, sb, row0, col0, tid, wm, wn, lane);

        size_t base = (size_t)ctaLin * 4096 + tid;
#pragma unroll
        for (int mi = 0; mi < 4; mi++) {
            uint32_t su[16];
#pragma unroll
            for (int nj = 0; nj < 4; nj++) {
                uint4 v = g_slog[base + (size_t)(mi * 4 + nj) * 256];
                su[4 * nj] = v.x; su[4 * nj + 1] = v.y;
                su[4 * nj + 2] = v.z; su[4 * nj + 3] = v.w;
            }
#pragma unroll
            for (int h = 0; h < 2; h++) {
                float d = 0.f, tsq = 0.f;
#pragma unroll
                for (int ni = 0; ni < 8; ni++) {
                    uint32_t u = su[ni * 2 + h];
                    float s0 = __uint_as_float(u << 16);
                    float s1 = __uint_as_float(u & 0xffff0000u);
                    float t0 = acc[mi][ni][h * 2];
                    float t1 = acc[mi][ni][h * 2 + 1];
                    d = fmaf(s0, t0, d); d = fmaf(s1, t1, d);
                    tsq = fmaf(t0, t0, tsq); tsq = fmaf(t1, t1, tsq);
                }
#pragma unroll
                for (int off = 1; off < 4; off <<= 1) {
                    d   += __shfl_xor_sync(0xffffffffu, d, off);
                    tsq += __shfl_xor_sync(0xffffffffu, tsq, off);
                }
                if ((lane & 3) == 0) {
                    int row = row0 + wm * 64 + mi * 16 + h * 8 + (lane >> 2);
                    size_t idx = (size_t)row * NPAD + nt * 4 + wn;
                    g_d[idx] = d; g_tt[idx] = tsq;
                }
            }
        }
    }
}

// ---------------- K2: combine + fused last-block finalize ----------------
#define CITER 16   // ceil(NT4 / 32)

__global__ void combine_kernel(const int* __restrict__ tgt,
                               const float* __restrict__ s_in,
                               const float* __restrict__ s_w,
                               float* __restrict__ out)
{
    int gw = (blockIdx.x * blockDim.x + threadIdx.x) >> 5;
    int lane = threadIdx.x & 31;
    const int row = gw;

    if (gw < BT) {
        float om[CITER], oz[CITER];
        float d = 0.f, ssq = 0.f, tsq = 0.f;
#pragma unroll
        for (int k = 0; k < CITER; k++) {
            int n = lane + k * 32;
            bool v = (n < NT4);
            size_t idx = (size_t)row * NPAD + n;
            om[k] = v ? g_m[idx] : -FLT_MAX;
            oz[k] = v ? g_z[idx] : 0.f;
            if (v) {
                d   += g_d[idx];
                ssq += g_ss[idx];
                tsq += g_tt[idx];
            }
        }
        float m = om[0];
#pragma unroll
        for (int k = 1; k < CITER; k++) m = fmaxf(m, om[k]);
#pragma unroll
        for (int off = 16; off > 0; off >>= 1)
            m = fmaxf(m, __shfl_xor_sync(0xffffffffu, m, off));
        float z = 0.f;
#pragma unroll
        for (int k = 0; k < CITER; k++)
            z += oz[k] * __expf(om[k] - m);     // independent exps, full issue
#pragma unroll
        for (int off = 16; off > 0; off >>= 1) {
            z   += __shfl_xor_sync(0xffffffffu, z, off);
            d   += __shfl_xor_sync(0xffffffffu, d, off);
            ssq += __shfl_xor_sync(0xffffffffu, ssq, off);
            tsq += __shfl_xor_sync(0xffffffffu, tsq, off);
        }

        bool is64 = (tgt[1] == -1);            // int64 layout: high word of -100
        int t = is64 ? tgt[2 * row] : tgt[row];

        float ce = 0.f;
        if (t >= 0) {
            float p = 0.f;
            const float* a = s_in + (size_t)row * KS;
            const float* w = s_w + (size_t)t * KS;
            for (int k = lane * 4; k < KS; k += 128) {
                float4 va = *reinterpret_cast<const float4*>(&a[k]);
                float4 vw = *reinterpret_cast<const float4*>(&w[k]);
                p += va.x * vw.x + va.y * vw.y + va.z * vw.z + va.w * vw.w;
            }
#pragma unroll
            for (int off = 16; off > 0; off >>= 1)
                p += __shfl_xor_sync(0xffffffffu, p, off);
            ce = (m + __logf(z)) - p;
        }
        float cs = d / (fmaxf(sqrtf(ssq), 1e-12f) * fmaxf(sqrtf(tsq), 1e-12f));
        if (lane == 0) { g_row[2 * row] = ce; g_row[2 * row + 1] = cs; }
    }

    // ---- fused finalize: last block reduces g_row deterministically ----
    __syncthreads();
    __shared__ int isLast;
    if (threadIdx.x == 0) {
        __threadfence();
        isLast = (atomicAdd(&g_cdone, 1) == NCOMB - 1);
    }
    __syncthreads();
    if (isLast) {
        __shared__ float sce[256], scs[256];
        int tid = threadIdx.x;
        float ce = 0.f, cs = 0.f;
        for (int r = tid; r < BT; r += 256) {
            ce += g_row[2 * r];
            cs += 1.0f - g_row[2 * r + 1];
        }
        sce[tid] = ce; scs[tid] = cs;
        __syncthreads();
        for (int s = 128; s > 0; s >>= 1) {
            if (tid < s) { sce[tid] += sce[tid + s]; scs[tid] += scs[tid + s]; }
            __syncthreads();
        }
        if (tid == 0)
            out[0] = 0.5f * (sce[0] / (float)BT) + 0.25f * (scs[0] / (float)BT);
    }
}

// ---------------- launch ----------------
extern "C" void kernel_launch(void* const* d_in, const int* in_sizes, int n_in,
                              void* d_out, int out_size)
{
    const float* s_in = (const float*)d_in[0];
    const float* t_in = (const float*)d_in[1];
    const float* s_w  = (const float*)d_in[2];
    const float* t_w  = (const float*)d_in[3];
    const int*   tgt  = (const int*)d_in[4];
    float* out = (float*)d_out;

    cudaFuncSetAttribute(gemm_fused_kernel,
                         cudaFuncAttributeMaxDynamicSharedMemorySize, SMEM_BYTES);

    cvt_all_kernel<<<CVT_GRID, 256>>>(s_in, t_in, s_w, t_w);

    gemm_fused_kernel<<<2 * NCTA, 256, SMEM_BYTES>>>();

    combine_kernel<<<NCOMB, 256>>>(tgt, s_in, s_w, out);
}